// round 4
// baseline (speedup 1.0000x reference)
#include <cuda_runtime.h>
#include <cstdint>
#include <cstddef>

typedef unsigned long long ull;

// ---------------- scratch (static device globals; no runtime alloc) ----------
__device__ __align__(16) float g_Wh[8192 * 256];   // [b*1024+n][h*32+d]  (8 MB)
__device__ __align__(16) float g_e1[65536];        // [(b*8+h)*1024 + n]
__device__ __align__(16) float g_e2[65536];
__device__ float g_C[64];                          // per (b,h) softmax shift
__device__ __align__(16) unsigned int g_adjbits[8 * 1024 * 32];  // 1 MB bitmask

// ---------------- packed fp32x2 helpers (FFMA2 via PTX) ----------------------
__device__ __forceinline__ ull ffma2(ull a, ull b, ull c) {
    ull d;
    asm("fma.rn.f32x2 %0, %1, %2, %3;" : "=l"(d) : "l"(a), "l"(b), "l"(c));
    return d;
}
__device__ __forceinline__ ull packf2(float x) {
    ull d;
    asm("mov.b64 %0, {%1, %1};" : "=l"(d) : "f"(x));
    return d;
}
__device__ __forceinline__ void unpackf2(ull v, float& lo, float& hi) {
    asm("mov.b64 {%0, %1}, %2;" : "=f"(lo), "=f"(hi) : "l"(v));
}
__device__ __forceinline__ void cp16(uint32_t dst, const float* src) {
    asm volatile("cp.async.cg.shared.global [%0], [%1], 16;" :: "r"(dst), "l"(src));
}
__device__ __forceinline__ void cp_commit() {
    asm volatile("cp.async.commit_group;");
}
template <int N> __device__ __forceinline__ void cp_wait() {
    asm volatile("cp.async.wait_group %0;" :: "n"(N));
}

// ---------------- Kernel A: Wh = X @ W  (8192 x 256 x 256 GEMM) --------------
__global__ __launch_bounds__(256) void gemm_wh_k(const float* __restrict__ X,
                                                 const float* __restrict__ W) {
    __shared__ __align__(16) float As[16][64];
    __shared__ __align__(16) float Bs[16][64];
    const int bm = blockIdx.x;
    const int bn = blockIdx.y;
    const int t  = threadIdx.x;
    const int ty = t >> 4;
    const int tx = t & 15;

    ull acc[4][2];
#pragma unroll
    for (int i = 0; i < 4; i++) { acc[i][0] = 0ull; acc[i][1] = 0ull; }

    for (int k0 = 0; k0 < 256; k0 += 16) {
        {
            int r  = t >> 2;
            int kc = (t & 3) * 4;
            float4 v = *reinterpret_cast<const float4*>(
                X + ((size_t)bm * 64 + r) * 256 + k0 + kc);
            As[kc + 0][r] = v.x; As[kc + 1][r] = v.y;
            As[kc + 2][r] = v.z; As[kc + 3][r] = v.w;
        }
        {
            int kk = t >> 4;
            int cc = (t & 15) * 4;
            int c  = bn * 64 + cc;
            *reinterpret_cast<float4*>(&Bs[kk][cc]) =
                *reinterpret_cast<const float4*>(
                    W + ((size_t)(c >> 5) * 256 + k0 + kk) * 32 + (c & 31));
        }
        __syncthreads();
#pragma unroll
        for (int k = 0; k < 16; k++) {
            float4    av = *reinterpret_cast<const float4*>(&As[k][ty * 4]);
            longlong2 bv = *reinterpret_cast<const longlong2*>(&Bs[k][tx * 4]);
            ull a0 = packf2(av.x), a1 = packf2(av.y), a2 = packf2(av.z), a3 = packf2(av.w);
            acc[0][0] = ffma2(a0, (ull)bv.x, acc[0][0]); acc[0][1] = ffma2(a0, (ull)bv.y, acc[0][1]);
            acc[1][0] = ffma2(a1, (ull)bv.x, acc[1][0]); acc[1][1] = ffma2(a1, (ull)bv.y, acc[1][1]);
            acc[2][0] = ffma2(a2, (ull)bv.x, acc[2][0]); acc[2][1] = ffma2(a2, (ull)bv.y, acc[2][1]);
            acc[3][0] = ffma2(a3, (ull)bv.x, acc[3][0]); acc[3][1] = ffma2(a3, (ull)bv.y, acc[3][1]);
        }
        __syncthreads();
    }
#pragma unroll
    for (int i = 0; i < 4; i++) {
        float4 o;
        unpackf2(acc[i][0], o.x, o.y);
        unpackf2(acc[i][1], o.z, o.w);
        *reinterpret_cast<float4*>(
            g_Wh + ((size_t)bm * 64 + ty * 4 + i) * 256 + bn * 64 + tx * 4) = o;
    }
}

// ---------------- Kernel A2: bitpack adjacency (32 MB -> 1 MB) ---------------
__global__ __launch_bounds__(256) void bitpack_k(const int* __restrict__ adj) {
    const int w = blockIdx.x * 256 + threadIdx.x;
    const int4* p = reinterpret_cast<const int4*>(adj) + (size_t)w * 8;
    unsigned int bits = 0;
#pragma unroll
    for (int k = 0; k < 8; k++) {
        int4 v = p[k];
        bits |= (unsigned)(v.x != 0) << (k * 4 + 0);
        bits |= (unsigned)(v.y != 0) << (k * 4 + 1);
        bits |= (unsigned)(v.z != 0) << (k * 4 + 2);
        bits |= (unsigned)(v.w != 0) << (k * 4 + 3);
    }
    g_adjbits[w] = bits;
}

// ---------------- Kernel B: e1/e2 + per-(b,h) shift, fused -------------------
// grid 64 = (b,h); block 1024 = one n per thread
__global__ __launch_bounds__(1024) void calc_ec_k(const float* __restrict__ a) {
    const int bh = blockIdx.x;
    const int h  = bh & 7;
    const int b  = bh >> 3;
    const int n  = threadIdx.x;

    __shared__ __align__(16) float sa[64];
    __shared__ float sm1[32], sm2[32];
    if (n < 16)
        reinterpret_cast<float4*>(sa)[n] =
            reinterpret_cast<const float4*>(a + h * 64)[n];
    __syncthreads();

    const float* wp = g_Wh + ((size_t)b * 1024 + n) * 256 + h * 32;
    float e1 = 0.f, e2 = 0.f;
#pragma unroll
    for (int k4 = 0; k4 < 8; k4++) {
        float4 v = reinterpret_cast<const float4*>(wp)[k4];
        e1 += v.x * sa[k4 * 4 + 0] + v.y * sa[k4 * 4 + 1]
            + v.z * sa[k4 * 4 + 2] + v.w * sa[k4 * 4 + 3];
        e2 += v.x * sa[32 + k4 * 4 + 0] + v.y * sa[32 + k4 * 4 + 1]
            + v.z * sa[32 + k4 * 4 + 2] + v.w * sa[32 + k4 * 4 + 3];
    }
    g_e1[bh * 1024 + n] = e1;
    g_e2[bh * 1024 + n] = e2;

    float m1 = e1, m2 = e2;
#pragma unroll
    for (int off = 16; off; off >>= 1) {
        m1 = fmaxf(m1, __shfl_xor_sync(0xffffffffu, m1, off));
        m2 = fmaxf(m2, __shfl_xor_sync(0xffffffffu, m2, off));
    }
    if ((n & 31) == 0) { sm1[n >> 5] = m1; sm2[n >> 5] = m2; }
    __syncthreads();
    if (n < 32) {
        m1 = sm1[n]; m2 = sm2[n];
#pragma unroll
        for (int off = 16; off; off >>= 1) {
            m1 = fmaxf(m1, __shfl_xor_sync(0xffffffffu, m1, off));
            m2 = fmaxf(m2, __shfl_xor_sync(0xffffffffu, m2, off));
        }
        if (n == 0) {
            float s = m1 + m2;
            g_C[bh] = fmaxf(s, 0.2f * s);
        }
    }
}

// ---------------- Kernel D: fused masked-softmax + attn@Wh + epilogue --------
// Block: 256 threads = 8 warps (warp == head), 16 i-rows. Grid: (64, 8).
// Warp-local cp.async double-buffered Wh staging; NO __syncthreads anywhere.
__global__ __launch_bounds__(256, 4) void gat_main_k(const float* __restrict__ bias,
                                                     float* __restrict__ out) {
    const int b    = blockIdx.y;
    const int i0   = blockIdx.x * 16;
    const int t    = threadIdx.x;
    const int h    = t >> 5;
    const int lane = t & 31;
    const int ig   = lane >> 3;   // FMA: 4 groups of 4 i-rows
    const int dg   = lane & 7;    // FMA: 8 groups of 4 dims
    const int il   = lane & 15;   // p:   i-row
    const int jh   = lane >> 4;   // p:   j-half (8 j's each)

    __shared__ __align__(16) float  sWh[2][8][16][32];  // 32 KB
    __shared__ __align__(16) float2 sPd[8][16][16];     // 16 KB  (total 48 KB)

    const int   bh    = b * 8 + h;
    const float Ch    = g_C[bh];
    const float my_e1 = g_e1[bh * 1024 + i0 + il];
    const float* __restrict__ e2B = g_e2 + bh * 1024;
    const float* __restrict__ WhB = g_Wh + ((size_t)b << 10) * 256 + h * 32;
    const unsigned int* __restrict__ mrow = g_adjbits + ((size_t)b * 1024 + i0 + il) * 32;

    // cp.async lane mapping: 4 x 16B per lane covers 16 rows x 128B
    const int cpRow = lane >> 3;          // + q*4
    const int cpSeg = (lane & 7) * 4;     // float offset within 128B row
    uint32_t sBase[2];
    sBase[0] = (uint32_t)__cvta_generic_to_shared(&sWh[0][h][cpRow][cpSeg]);
    sBase[1] = (uint32_t)__cvta_generic_to_shared(&sWh[1][h][cpRow][cpSeg]);
    const float* gBase = WhB + (size_t)cpRow * 256 + cpSeg;

#define ISSUE_CHUNK(J0, BUF)                                              \
    {                                                                     \
        const float* gp = gBase + (size_t)(J0) * 256;                     \
        uint32_t     sp = sBase[BUF];                                     \
        cp16(sp,            gp);                                          \
        cp16(sp + 4 * 128,  gp + 4 * 256);                                \
        cp16(sp + 8 * 128,  gp + 8 * 256);                                \
        cp16(sp + 12 * 128, gp + 12 * 256);                               \
    }

    ISSUE_CHUNK(0, 0)  cp_commit();
    ISSUE_CHUNK(16, 1) cp_commit();

    float den = 0.f;
    ull acc[8];
#pragma unroll
    for (int k = 0; k < 8; k++) acc[k] = 0ull;

    unsigned int mword = 0;
#pragma unroll 2
    for (int j0 = 0; j0 < 1024; j0 += 16) {
        const int buf = (j0 >> 4) & 1;
        cp_wait<1>();      // chunk j0 landed
        __syncwarp();      // make all lanes' copies visible warp-wide

        // ---- p phase: thread (h, il, jh) computes p for 8 j's ----
        if ((j0 & 16) == 0) mword = mrow[j0 >> 5];
        unsigned int mbits = mword >> ((j0 & 16) + jh * 8);
        const float4* e2p = reinterpret_cast<const float4*>(e2B + j0 + jh * 8);
        float4 ea = e2p[0], eb = e2p[1];
#define DO_P(K, EV)                                                       \
        {                                                                 \
            float s = my_e1 + (EV);                                       \
            float l = fmaxf(s, 0.2f * s);                                 \
            float p = ((mbits >> (K)) & 1u) ? __expf(l - Ch) : 0.f;       \
            den += p;                                                     \
            sPd[h][jh * 8 + (K)][il] = make_float2(p, p);                 \
        }
        DO_P(0, ea.x) DO_P(1, ea.y) DO_P(2, ea.z) DO_P(3, ea.w)
        DO_P(4, eb.x) DO_P(5, eb.y) DO_P(6, eb.z) DO_P(7, eb.w)
#undef DO_P
        __syncwarp();      // sPd produced/consumed within warp h only

        // ---- FMA phase: rank-16 update of [4 i x 4 d] accumulators ----
        const float* wrow = &sWh[buf][h][0][dg * 4];
#pragma unroll
        for (int jj = 0; jj < 16; jj++) {
            longlong2 w2 = *reinterpret_cast<const longlong2*>(wrow + jj * 32);
            longlong2 pA = *reinterpret_cast<const longlong2*>(&sPd[h][jj][ig * 4]);
            longlong2 pB = *reinterpret_cast<const longlong2*>(&sPd[h][jj][ig * 4 + 2]);
            acc[0] = ffma2((ull)pA.x, (ull)w2.x, acc[0]);
            acc[1] = ffma2((ull)pA.x, (ull)w2.y, acc[1]);
            acc[2] = ffma2((ull)pA.y, (ull)w2.x, acc[2]);
            acc[3] = ffma2((ull)pA.y, (ull)w2.y, acc[3]);
            acc[4] = ffma2((ull)pB.x, (ull)w2.x, acc[4]);
            acc[5] = ffma2((ull)pB.x, (ull)w2.y, acc[5]);
            acc[6] = ffma2((ull)pB.y, (ull)w2.x, acc[6]);
            acc[7] = ffma2((ull)pB.y, (ull)w2.y, acc[7]);
        }
        __syncwarp();      // FMA reads done before buffer refill
        if (j0 < 1024 - 32) ISSUE_CHUNK(j0 + 32, buf)
        cp_commit();       // commit (possibly empty) to keep group counts aligned
    }
#undef ISSUE_CHUNK

    // den: combine j-halves; row il total ends up in lane il (0..15)
    den += __shfl_xor_sync(0xffffffffu, den, 16);

    // epilogue: out = relu(num/den + bias)
    float4 bi = *reinterpret_cast<const float4*>(bias + h * 32 + dg * 4);
#pragma unroll
    for (int r = 0; r < 4; r++) {
        int   i    = ig * 4 + r;
        float dsum = __shfl_sync(0xffffffffu, den, i);
        float rd   = 1.0f / dsum;
        float v0, v1, v2, v3;
        unpackf2(acc[2 * r],     v0, v1);
        unpackf2(acc[2 * r + 1], v2, v3);
        float4 o;
        o.x = fmaxf(v0 * rd + bi.x, 0.f);
        o.y = fmaxf(v1 * rd + bi.y, 0.f);
        o.z = fmaxf(v2 * rd + bi.z, 0.f);
        o.w = fmaxf(v3 * rd + bi.w, 0.f);
        *reinterpret_cast<float4*>(
            out + (((size_t)b << 10) + i0 + i) * 256 + h * 32 + dg * 4) = o;
    }
}

// ---------------- launcher ---------------------------------------------------
extern "C" void kernel_launch(void* const* d_in, const int* in_sizes, int n_in,
                              void* d_out, int out_size) {
    const float* nf   = (const float*)d_in[0];   // (8,1024,256)
    const int*   adj  = (const int*)d_in[1];     // (8,1024,1024)
    const float* W    = (const float*)d_in[2];   // (8,256,32)
    const float* a    = (const float*)d_in[3];   // (8,64)
    const float* bias = (const float*)d_in[4];   // (256,)
    float*       out  = (float*)d_out;           // (8,1024,256)

    bitpack_k<<<1024, 256>>>(adj);
    gemm_wh_k<<<dim3(128, 4), 256>>>(nf, W);
    calc_ec_k<<<64, 1024>>>(a);
    gat_main_k<<<dim3(64, 8), 256>>>(bias, out);
}

// round 7
// speedup vs baseline: 2.0052x; 2.0052x over previous
#include <cuda_runtime.h>
#include <cuda_bf16.h>
#include <cstdint>
#include <cstddef>

typedef unsigned long long ull;

// ---------------- scratch (static device globals; no runtime alloc) ----------
__device__ __align__(16) float g_Wh[8192 * 256];       // [b*1024+n][h*32+d]
__device__ __align__(16) float g_e1[65536];            // [(b*8+h)*1024 + n]
__device__ __align__(16) float g_e2[65536];
__device__ float g_C[64];
__device__ __align__(16) unsigned g_adjbits[8 * 1024 * 32];          // 1 MB
__device__ __align__(16) __nv_bfloat16 g_WhT_hi[64 * 32 * 1024];     // [bh][d][n]
__device__ __align__(16) __nv_bfloat16 g_WhT_lo[64 * 32 * 1024];

// ---------------- small PTX helpers ------------------------------------------
__device__ __forceinline__ ull ffma2(ull a, ull b, ull c) {
    ull d; asm("fma.rn.f32x2 %0, %1, %2, %3;" : "=l"(d) : "l"(a), "l"(b), "l"(c)); return d;
}
__device__ __forceinline__ ull packf2(float x) {
    ull d; asm("mov.b64 %0, {%1, %1};" : "=l"(d) : "f"(x)); return d;
}
__device__ __forceinline__ void unpackf2(ull v, float& lo, float& hi) {
    asm("mov.b64 {%0, %1}, %2;" : "=f"(lo), "=f"(hi) : "l"(v));
}
__device__ __forceinline__ uint32_t s2u(const void* p) {
    return (uint32_t)__cvta_generic_to_shared(p);
}
__device__ __forceinline__ void cp16(uint32_t dst, const void* src) {
    asm volatile("cp.async.cg.shared.global [%0], [%1], 16;" :: "r"(dst), "l"(src));
}
__device__ __forceinline__ void cp_commit() { asm volatile("cp.async.commit_group;"); }
template <int N> __device__ __forceinline__ void cp_wait() {
    asm volatile("cp.async.wait_group %0;" :: "n"(N));
}
__device__ __forceinline__ float ex2f(float x) {
    float r; asm("ex2.approx.ftz.f32 %0, %1;" : "=f"(r) : "f"(x)); return r;
}
// pack: result.hi = bf16(h), result.lo = bf16(l)
__device__ __forceinline__ uint32_t cvt2bf(float h, float l) {
    uint32_t r; asm("cvt.rn.bf16x2.f32 %0, %1, %2;" : "=r"(r) : "f"(h), "f"(l)); return r;
}
// D(16x8,f32) += A(16x16,bf16,row) * B(16x8,bf16,col)
__device__ __forceinline__ void mma16816(float* d,
                                         uint32_t a0, uint32_t a1, uint32_t a2, uint32_t a3,
                                         uint32_t b0, uint32_t b1) {
    asm volatile(
        "mma.sync.aligned.m16n8k16.row.col.f32.bf16.bf16.f32 "
        "{%0,%1,%2,%3}, {%4,%5,%6,%7}, {%8,%9}, {%0,%1,%2,%3};"
        : "+f"(d[0]), "+f"(d[1]), "+f"(d[2]), "+f"(d[3])
        : "r"(a0), "r"(a1), "r"(a2), "r"(a3), "r"(b0), "r"(b1));
}

// ---------------- Kernel A: Wh = X @ W  (8192 x 256 x 256 GEMM) --------------
__global__ __launch_bounds__(256) void gemm_wh_k(const float* __restrict__ X,
                                                 const float* __restrict__ W) {
    __shared__ __align__(16) float As[16][64];
    __shared__ __align__(16) float Bs[16][64];
    const int bm = blockIdx.x;
    const int bn = blockIdx.y;
    const int t  = threadIdx.x;
    const int ty = t >> 4;
    const int tx = t & 15;

    ull acc[4][2];
#pragma unroll
    for (int i = 0; i < 4; i++) { acc[i][0] = 0ull; acc[i][1] = 0ull; }

    for (int k0 = 0; k0 < 256; k0 += 16) {
        {
            int r  = t >> 2;
            int kc = (t & 3) * 4;
            float4 v = *reinterpret_cast<const float4*>(
                X + ((size_t)bm * 64 + r) * 256 + k0 + kc);
            As[kc + 0][r] = v.x; As[kc + 1][r] = v.y;
            As[kc + 2][r] = v.z; As[kc + 3][r] = v.w;
        }
        {
            int kk = t >> 4;
            int cc = (t & 15) * 4;
            int c  = bn * 64 + cc;
            *reinterpret_cast<float4*>(&Bs[kk][cc]) =
                *reinterpret_cast<const float4*>(
                    W + ((size_t)(c >> 5) * 256 + k0 + kk) * 32 + (c & 31));
        }
        __syncthreads();
#pragma unroll
        for (int k = 0; k < 16; k++) {
            float4    av = *reinterpret_cast<const float4*>(&As[k][ty * 4]);
            longlong2 bv = *reinterpret_cast<const longlong2*>(&Bs[k][tx * 4]);
            ull a0 = packf2(av.x), a1 = packf2(av.y), a2 = packf2(av.z), a3 = packf2(av.w);
            acc[0][0] = ffma2(a0, (ull)bv.x, acc[0][0]); acc[0][1] = ffma2(a0, (ull)bv.y, acc[0][1]);
            acc[1][0] = ffma2(a1, (ull)bv.x, acc[1][0]); acc[1][1] = ffma2(a1, (ull)bv.y, acc[1][1]);
            acc[2][0] = ffma2(a2, (ull)bv.x, acc[2][0]); acc[2][1] = ffma2(a2, (ull)bv.y, acc[2][1]);
            acc[3][0] = ffma2(a3, (ull)bv.x, acc[3][0]); acc[3][1] = ffma2(a3, (ull)bv.y, acc[3][1]);
        }
        __syncthreads();
    }
#pragma unroll
    for (int i = 0; i < 4; i++) {
        float4 o;
        unpackf2(acc[i][0], o.x, o.y);
        unpackf2(acc[i][1], o.z, o.w);
        *reinterpret_cast<float4*>(
            g_Wh + ((size_t)bm * 64 + ty * 4 + i) * 256 + bn * 64 + tx * 4) = o;
    }
}

// ---------------- Kernel A2: bitpack adjacency -------------------------------
__global__ __launch_bounds__(256) void bitpack_k(const int* __restrict__ adj) {
    const int w = blockIdx.x * 256 + threadIdx.x;
    const int4* p = reinterpret_cast<const int4*>(adj) + (size_t)w * 8;
    unsigned bits = 0;
#pragma unroll
    for (int k = 0; k < 8; k++) {
        int4 v = p[k];
        bits |= (unsigned)(v.x != 0) << (k * 4 + 0);
        bits |= (unsigned)(v.y != 0) << (k * 4 + 1);
        bits |= (unsigned)(v.z != 0) << (k * 4 + 2);
        bits |= (unsigned)(v.w != 0) << (k * 4 + 3);
    }
    g_adjbits[w] = bits;
}

// ---------------- Kernel B: e1/e2 + per-(b,h) shift --------------------------
__global__ __launch_bounds__(1024) void calc_ec_k(const float* __restrict__ a) {
    const int bh = blockIdx.x;
    const int h  = bh & 7;
    const int b  = bh >> 3;
    const int n  = threadIdx.x;

    __shared__ __align__(16) float sa[64];
    __shared__ float sm1[32], sm2[32];
    if (n < 16)
        reinterpret_cast<float4*>(sa)[n] = reinterpret_cast<const float4*>(a + h * 64)[n];
    __syncthreads();

    const float* wp = g_Wh + ((size_t)b * 1024 + n) * 256 + h * 32;
    float e1 = 0.f, e2 = 0.f;
#pragma unroll
    for (int k4 = 0; k4 < 8; k4++) {
        float4 v = reinterpret_cast<const float4*>(wp)[k4];
        e1 += v.x * sa[k4 * 4 + 0] + v.y * sa[k4 * 4 + 1]
            + v.z * sa[k4 * 4 + 2] + v.w * sa[k4 * 4 + 3];
        e2 += v.x * sa[32 + k4 * 4 + 0] + v.y * sa[32 + k4 * 4 + 1]
            + v.z * sa[32 + k4 * 4 + 2] + v.w * sa[32 + k4 * 4 + 3];
    }
    g_e1[bh * 1024 + n] = e1;
    g_e2[bh * 1024 + n] = e2;

    float m1 = e1, m2 = e2;
#pragma unroll
    for (int off = 16; off; off >>= 1) {
        m1 = fmaxf(m1, __shfl_xor_sync(0xffffffffu, m1, off));
        m2 = fmaxf(m2, __shfl_xor_sync(0xffffffffu, m2, off));
    }
    if ((n & 31) == 0) { sm1[n >> 5] = m1; sm2[n >> 5] = m2; }
    __syncthreads();
    if (n < 32) {
        m1 = sm1[n]; m2 = sm2[n];
#pragma unroll
        for (int off = 16; off; off >>= 1) {
            m1 = fmaxf(m1, __shfl_xor_sync(0xffffffffu, m1, off));
            m2 = fmaxf(m2, __shfl_xor_sync(0xffffffffu, m2, off));
        }
        if (n == 0) {
            float s = m1 + m2;
            g_C[bh] = fmaxf(s, 0.2f * s);
        }
    }
}

// ---------------- Kernel B2: transpose + bf16-split Wh -----------------------
__global__ __launch_bounds__(256) void whT_k() {
    __shared__ float sT[32][132];
    const int bh = blockIdx.x;
    const int n0 = blockIdx.y * 128;
    const int h  = bh & 7, b = bh >> 3;
    const int t  = threadIdx.x;
    {
        const int r = t >> 1, part = t & 1;
        const float4* src = reinterpret_cast<const float4*>(
            g_Wh + ((size_t)(b * 1024 + n0 + r)) * 256 + h * 32 + part * 16);
#pragma unroll
        for (int q = 0; q < 4; q++) {
            float4 v = src[q];
            int d = part * 16 + q * 4;
            sT[d + 0][r] = v.x; sT[d + 1][r] = v.y;
            sT[d + 2][r] = v.z; sT[d + 3][r] = v.w;
        }
    }
    __syncthreads();
    {
        const int d = t >> 3, seg = t & 7;
        const float4* rp = reinterpret_cast<const float4*>(&sT[d][seg * 16]);
        uint32_t H[8], L[8];
#pragma unroll
        for (int q = 0; q < 4; q++) {
            float4 v = rp[q];
            uint32_t h0 = cvt2bf(v.y, v.x);
            uint32_t h1 = cvt2bf(v.w, v.z);
            float r0 = v.x - __uint_as_float(h0 << 16);
            float r1 = v.y - __uint_as_float(h0 & 0xffff0000u);
            float r2 = v.z - __uint_as_float(h1 << 16);
            float r3 = v.w - __uint_as_float(h1 & 0xffff0000u);
            H[q * 2] = h0; H[q * 2 + 1] = h1;
            L[q * 2] = cvt2bf(r1, r0); L[q * 2 + 1] = cvt2bf(r3, r2);
        }
        uint4* dh = reinterpret_cast<uint4*>(g_WhT_hi + (size_t)bh * 32768 + d * 1024 + n0 + seg * 16);
        uint4* dl = reinterpret_cast<uint4*>(g_WhT_lo + (size_t)bh * 32768 + d * 1024 + n0 + seg * 16);
        dh[0] = make_uint4(H[0], H[1], H[2], H[3]);
        dh[1] = make_uint4(H[4], H[5], H[6], H[7]);
        dl[0] = make_uint4(L[0], L[1], L[2], L[3]);
        dl[1] = make_uint4(L[4], L[5], L[6], L[7]);
    }
}

// ---------------- Kernel D: HMMA fused softmax + attn@Wh ---------------------
// Grid (8 i-tiles, 64 bh), 256 threads = 8 warps. Warp w owns rows w*16..w*16+15.
// P is computed directly in mma.sync A-fragment layout (never hits smem).
// B (WhT hi/lo) staged via cp.async double buffer, bank-pad stride 72 bf16.
__global__ __launch_bounds__(256, 2) void gat_mma_k(const float* __restrict__ bias,
                                                    float* __restrict__ out) {
    __shared__ __align__(16) __nv_bfloat16 sB[2][2][32][72];  // [buf][hi/lo][d][j]

    const int t    = threadIdx.x;
    const int w    = t >> 5;
    const int lane = t & 31;
    const int bh   = blockIdx.y;
    const int b    = bh >> 3, h = bh & 7;
    const int i0   = blockIdx.x * 128;

    const int r0 = lane >> 2;        // fragment row (and b-frag n within ntile)
    const int c0 = (lane & 3) * 2;   // fragment k-col pair base

    const int   row0 = w * 16 + r0;  // block-local rows row0, row0+8
    const float C    = g_C[bh];
    const float K1 = 1.44269504f, K2 = 0.2f * 1.44269504f;
    const float e1_0 = g_e1[bh * 1024 + i0 + row0];
    const float e1_1 = g_e1[bh * 1024 + i0 + row0 + 8];
    const float c1_0 = e1_0 * K1 - C * K1, c2_0 = e1_0 * K2 - C * K1;
    const float c1_1 = e1_1 * K1 - C * K1, c2_1 = e1_1 * K2 - C * K1;

    const unsigned* __restrict__ mrow0 = g_adjbits + (size_t)(b * 1024 + i0 + row0) * 32;
    const unsigned* __restrict__ mrow1 = mrow0 + 8 * 32;
    const float* __restrict__ e2B = g_e2 + bh * 1024;

    // cp.async mapping: thread t stages d = t>>3, 8 j's at (t&7)*8
    const int cpd = t >> 3, cpj = (t & 7) * 8;
    const __nv_bfloat16* bsrc_hi = g_WhT_hi + (size_t)bh * 32768 + cpd * 1024 + cpj;
    const __nv_bfloat16* bsrc_lo = g_WhT_lo + (size_t)bh * 32768 + cpd * 1024 + cpj;
#define CP_B(C_)                                                              \
    {                                                                         \
        int bb = (C_) & 1;                                                    \
        cp16(s2u(&sB[bb][0][cpd][cpj]), bsrc_hi + (C_) * 64);                 \
        cp16(s2u(&sB[bb][1][cpd][cpj]), bsrc_lo + (C_) * 64);                 \
    }
    CP_B(0) cp_commit();
    CP_B(1) cp_commit();

    float acc[4][4];
#pragma unroll
    for (int nt = 0; nt < 4; nt++)
#pragma unroll
        for (int q = 0; q < 4; q++) acc[nt][q] = 0.f;
    float den0 = 0.f, den1 = 0.f;

    for (int c = 0; c < 16; c++) {
        cp_wait<1>();
        __syncthreads();                      // buffer c ready for all warps
        const int buf = c & 1;

        const unsigned m0a = mrow0[2 * c], m0b = mrow0[2 * c + 1];
        const unsigned m1a = mrow1[2 * c], m1b = mrow1[2 * c + 1];

#pragma unroll
        for (int kt = 0; kt < 4; kt++) {
            const int jb = c * 64 + kt * 16;
            float2 eA = *reinterpret_cast<const float2*>(e2B + jb + c0);
            float2 eB = *reinterpret_cast<const float2*>(e2B + jb + c0 + 8);
            const int sh = ((kt & 1) * 16) + c0;
            const unsigned bits0 = ((kt >> 1) ? m0b : m0a) >> sh;
            const unsigned bits1 = ((kt >> 1) ? m1b : m1a) >> sh;

#define PP(DST, CONV1, CONV2, EV, BITS, POS)                                  \
            float DST;                                                        \
            {                                                                 \
                float s1 = fmaf((EV), K1, CONV1);                             \
                float s2 = fmaf((EV), K2, CONV2);                             \
                float e  = ex2f(fmaxf(s1, s2));                               \
                DST = (((BITS) >> (POS)) & 1u) ? e : 0.f;                     \
            }
            PP(p00, c1_0, c2_0, eA.x, bits0, 0)
            PP(p01, c1_0, c2_0, eA.y, bits0, 1)
            PP(p08, c1_0, c2_0, eB.x, bits0, 8)
            PP(p09, c1_0, c2_0, eB.y, bits0, 9)
            PP(p10, c1_1, c2_1, eA.x, bits1, 0)
            PP(p11, c1_1, c2_1, eA.y, bits1, 1)
            PP(p18, c1_1, c2_1, eB.x, bits1, 8)
            PP(p19, c1_1, c2_1, eB.y, bits1, 9)
#undef PP
            den0 += (p00 + p01) + (p08 + p09);
            den1 += (p10 + p11) + (p18 + p19);

            // A fragments: hi + lo split
            uint32_t ah0 = cvt2bf(p01, p00);
            uint32_t ah1 = cvt2bf(p11, p10);
            uint32_t ah2 = cvt2bf(p09, p08);
            uint32_t ah3 = cvt2bf(p19, p18);
            uint32_t al0 = cvt2bf(p01 - __uint_as_float(ah0 & 0xffff0000u),
                                  p00 - __uint_as_float(ah0 << 16));
            uint32_t al1 = cvt2bf(p11 - __uint_as_float(ah1 & 0xffff0000u),
                                  p10 - __uint_as_float(ah1 << 16));
            uint32_t al2 = cvt2bf(p09 - __uint_as_float(ah2 & 0xffff0000u),
                                  p08 - __uint_as_float(ah2 << 16));
            uint32_t al3 = cvt2bf(p19 - __uint_as_float(ah3 & 0xffff0000u),
                                  p18 - __uint_as_float(ah3 << 16));

#pragma unroll
            for (int nt = 0; nt < 4; nt++) {
                const __nv_bfloat16* bp_h = &sB[buf][0][nt * 8 + r0][kt * 16 + c0];
                const __nv_bfloat16* bp_l = &sB[buf][1][nt * 8 + r0][kt * 16 + c0];
                uint32_t bh0 = *reinterpret_cast<const uint32_t*>(bp_h);
                uint32_t bh1 = *reinterpret_cast<const uint32_t*>(bp_h + 8);
                uint32_t bl0 = *reinterpret_cast<const uint32_t*>(bp_l);
                uint32_t bl1 = *reinterpret_cast<const uint32_t*>(bp_l + 8);
                mma16816(acc[nt], ah0, ah1, ah2, ah3, bh0, bh1);
                mma16816(acc[nt], ah0, ah1, ah2, ah3, bl0, bl1);
                mma16816(acc[nt], al0, al1, al2, al3, bh0, bh1);
            }
        }
        __syncthreads();                      // all warps done reading buf
        if (c < 14) CP_B(c + 2)
        cp_commit();
    }
#undef CP_B

    // quad-reduce den (lanes sharing the same fragment row)
    den0 += __shfl_xor_sync(0xffffffffu, den0, 1);
    den0 += __shfl_xor_sync(0xffffffffu, den0, 2);
    den1 += __shfl_xor_sync(0xffffffffu, den1, 1);
    den1 += __shfl_xor_sync(0xffffffffu, den1, 2);
    const float rd0 = 1.0f / den0;
    const float rd1 = 1.0f / den1;

    // epilogue straight from D fragments
    float* o0 = out + ((size_t)(b * 1024 + i0 + row0)) * 256 + h * 32;
    float* o1 = o0 + 8 * 256;
#pragma unroll
    for (int nt = 0; nt < 4; nt++) {
        const int dcol = nt * 8 + c0;
        float2 bi = *reinterpret_cast<const float2*>(bias + h * 32 + dcol);
        float2 v0, v1;
        v0.x = fmaxf(acc[nt][0] * rd0 + bi.x, 0.f);
        v0.y = fmaxf(acc[nt][1] * rd0 + bi.y, 0.f);
        v1.x = fmaxf(acc[nt][2] * rd1 + bi.x, 0.f);
        v1.y = fmaxf(acc[nt][3] * rd1 + bi.y, 0.f);
        *reinterpret_cast<float2*>(o0 + dcol) = v0;
        *reinterpret_cast<float2*>(o1 + dcol) = v1;
    }
}

// ---------------- launcher ---------------------------------------------------
extern "C" void kernel_launch(void* const* d_in, const int* in_sizes, int n_in,
                              void* d_out, int out_size) {
    const float* nf   = (const float*)d_in[0];   // (8,1024,256)
    const int*   adj  = (const int*)d_in[1];     // (8,1024,1024)
    const float* W    = (const float*)d_in[2];   // (8,256,32)
    const float* a    = (const float*)d_in[3];   // (8,64)
    const float* bias = (const float*)d_in[4];   // (256,)
    float*       out  = (float*)d_out;           // (8,1024,256)

    bitpack_k<<<1024, 256>>>(adj);
    gemm_wh_k<<<dim3(128, 4), 256>>>(nf, W);
    calc_ec_k<<<64, 1024>>>(a);
    whT_k<<<dim3(64, 8), 256>>>();
    gat_mma_k<<<dim3(8, 64), 256>>>(bias, out);
}

// round 8
// speedup vs baseline: 2.1314x; 1.0629x over previous
#include <cuda_runtime.h>
#include <cuda_bf16.h>
#include <cstdint>
#include <cstddef>

typedef unsigned long long ull;

// ---------------- scratch (static device globals; no runtime alloc) ----------
__device__ __align__(16) float g_Wh[8192 * 256];       // [b*1024+n][h*32+d]
__device__ __align__(16) float g_e1[65536];            // [(b*8+h)*1024 + n]
__device__ __align__(16) float g_e2[65536];
__device__ __align__(16) float g_M1[256];              // per (bh, quarter) max e1
__device__ __align__(16) float g_M2[256];              // per (bh, quarter) max e2
__device__ __align__(16) unsigned g_adjbits[8 * 1024 * 32];          // 1 MB
// WhT stored j-interleaved within 16-groups: phys order (0,1,8,9,2,3,10,11,...)
__device__ __align__(16) __nv_bfloat16 g_WhT_hi[64 * 32 * 1024];     // [bh][d][n]
__device__ __align__(16) __nv_bfloat16 g_WhT_lo[64 * 32 * 1024];

// ---------------- small PTX helpers ------------------------------------------
__device__ __forceinline__ ull ffma2(ull a, ull b, ull c) {
    ull d; asm("fma.rn.f32x2 %0, %1, %2, %3;" : "=l"(d) : "l"(a), "l"(b), "l"(c)); return d;
}
__device__ __forceinline__ ull packf2(float x) {
    ull d; asm("mov.b64 %0, {%1, %1};" : "=l"(d) : "f"(x)); return d;
}
__device__ __forceinline__ void unpackf2(ull v, float& lo, float& hi) {
    asm("mov.b64 {%0, %1}, %2;" : "=f"(lo), "=f"(hi) : "l"(v));
}
__device__ __forceinline__ uint32_t s2u(const void* p) {
    return (uint32_t)__cvta_generic_to_shared(p);
}
__device__ __forceinline__ void cp16(uint32_t dst, const void* src) {
    asm volatile("cp.async.cg.shared.global [%0], [%1], 16;" :: "r"(dst), "l"(src));
}
__device__ __forceinline__ void cp_commit() { asm volatile("cp.async.commit_group;"); }
template <int N> __device__ __forceinline__ void cp_wait() {
    asm volatile("cp.async.wait_group %0;" :: "n"(N));
}
__device__ __forceinline__ float ex2f(float x) {
    float r; asm("ex2.approx.ftz.f32 %0, %1;" : "=f"(r) : "f"(x)); return r;
}
// pack: result low-half = bf16(l), high-half = bf16(h)
__device__ __forceinline__ uint32_t cvt2bf(float h, float l) {
    uint32_t r; asm("cvt.rn.bf16x2.f32 %0, %1, %2;" : "=r"(r) : "f"(h), "f"(l)); return r;
}
// D(16x8,f32) += A(16x16,bf16,row) * B(16x8,bf16,col)
__device__ __forceinline__ void mma16816(float* d,
                                         uint32_t a0, uint32_t a1, uint32_t a2, uint32_t a3,
                                         uint32_t b0, uint32_t b1) {
    asm volatile(
        "mma.sync.aligned.m16n8k16.row.col.f32.bf16.bf16.f32 "
        "{%0,%1,%2,%3}, {%4,%5,%6,%7}, {%8,%9}, {%0,%1,%2,%3};"
        : "+f"(d[0]), "+f"(d[1]), "+f"(d[2]), "+f"(d[3])
        : "r"(a0), "r"(a1), "r"(a2), "r"(a3), "r"(b0), "r"(b1));
}

// ---------------- Kernel A: Wh = X @ W + fused transposed bf16 split ---------
// Writes g_Wh (fp32) and g_WhT_hi/lo (bf16, [bh][d][n], j-interleaved).
__global__ __launch_bounds__(256) void gemm_wh_k(const float* __restrict__ X,
                                                 const float* __restrict__ W) {
    __shared__ __align__(16) float As[16][64];
    __shared__ __align__(16) float Bs[16][64];
    __shared__ __align__(16) float sT[64][68];   // [col][row] transpose stage
    const int bm = blockIdx.x;   // 128 tiles of 64 rows
    const int bn = blockIdx.y;   // 4 tiles of 64 cols (= heads 2bn, 2bn+1)
    const int t  = threadIdx.x;
    const int ty = t >> 4;
    const int tx = t & 15;

    ull acc[4][2];
#pragma unroll
    for (int i = 0; i < 4; i++) { acc[i][0] = 0ull; acc[i][1] = 0ull; }

    for (int k0 = 0; k0 < 256; k0 += 16) {
        {
            int r  = t >> 2;
            int kc = (t & 3) * 4;
            float4 v = *reinterpret_cast<const float4*>(
                X + ((size_t)bm * 64 + r) * 256 + k0 + kc);
            As[kc + 0][r] = v.x; As[kc + 1][r] = v.y;
            As[kc + 2][r] = v.z; As[kc + 3][r] = v.w;
        }
        {
            int kk = t >> 4;
            int cc = (t & 15) * 4;
            int c  = bn * 64 + cc;
            *reinterpret_cast<float4*>(&Bs[kk][cc]) =
                *reinterpret_cast<const float4*>(
                    W + ((size_t)(c >> 5) * 256 + k0 + kk) * 32 + (c & 31));
        }
        __syncthreads();
#pragma unroll
        for (int k = 0; k < 16; k++) {
            float4    av = *reinterpret_cast<const float4*>(&As[k][ty * 4]);
            longlong2 bv = *reinterpret_cast<const longlong2*>(&Bs[k][tx * 4]);
            ull a0 = packf2(av.x), a1 = packf2(av.y), a2 = packf2(av.z), a3 = packf2(av.w);
            acc[0][0] = ffma2(a0, (ull)bv.x, acc[0][0]); acc[0][1] = ffma2(a0, (ull)bv.y, acc[0][1]);
            acc[1][0] = ffma2(a1, (ull)bv.x, acc[1][0]); acc[1][1] = ffma2(a1, (ull)bv.y, acc[1][1]);
            acc[2][0] = ffma2(a2, (ull)bv.x, acc[2][0]); acc[2][1] = ffma2(a2, (ull)bv.y, acc[2][1]);
            acc[3][0] = ffma2(a3, (ull)bv.x, acc[3][0]); acc[3][1] = ffma2(a3, (ull)bv.y, acc[3][1]);
        }
        __syncthreads();
    }

    // fp32 output + transpose staging
#pragma unroll
    for (int i = 0; i < 4; i++) {
        float4 o;
        unpackf2(acc[i][0], o.x, o.y);
        unpackf2(acc[i][1], o.z, o.w);
        *reinterpret_cast<float4*>(
            g_Wh + ((size_t)bm * 64 + ty * 4 + i) * 256 + bn * 64 + tx * 4) = o;
        int r = ty * 4 + i;
        sT[tx * 4 + 0][r] = o.x; sT[tx * 4 + 1][r] = o.y;
        sT[tx * 4 + 2][r] = o.z; sT[tx * 4 + 3][r] = o.w;
    }
    __syncthreads();

    // transposed bf16 hi/lo write, j-interleaved within 16-groups
    {
        const int c   = t >> 2;          // 0..63 (column = head-local dim)
        const int seg = t & 3;           // 16 rows each
        const int b   = bm >> 4;
        const int n0  = (bm & 15) * 64 + seg * 16;
        const int h   = 2 * bn + (c >> 5);
        const int d   = c & 31;
        float v[16];
        const float4* rp = reinterpret_cast<const float4*>(&sT[c][seg * 16]);
#pragma unroll
        for (int q = 0; q < 4; q++) {
            float4 f = rp[q];
            v[q * 4 + 0] = f.x; v[q * 4 + 1] = f.y;
            v[q * 4 + 2] = f.z; v[q * 4 + 3] = f.w;
        }
        const int perm[8] = {0, 8, 2, 10, 4, 12, 6, 14};
        uint32_t H[8], L[8];
#pragma unroll
        for (int m = 0; m < 8; m++) {
            float f0 = v[perm[m]], f1 = v[perm[m] + 1];
            uint32_t hw = cvt2bf(f1, f0);
            float r0 = f0 - __uint_as_float(hw << 16);
            float r1 = f1 - __uint_as_float(hw & 0xffff0000u);
            H[m] = hw;
            L[m] = cvt2bf(r1, r0);
        }
        const size_t off = (size_t)(b * 8 + h) * 32768 + (size_t)d * 1024 + n0;
        uint4* dh = reinterpret_cast<uint4*>(g_WhT_hi + off);
        uint4* dl = reinterpret_cast<uint4*>(g_WhT_lo + off);
        dh[0] = make_uint4(H[0], H[1], H[2], H[3]);
        dh[1] = make_uint4(H[4], H[5], H[6], H[7]);
        dl[0] = make_uint4(L[0], L[1], L[2], L[3]);
        dl[1] = make_uint4(L[4], L[5], L[6], L[7]);
    }
}

// ---------------- Kernel A2: bitpack adjacency -------------------------------
__global__ __launch_bounds__(256) void bitpack_k(const int* __restrict__ adj) {
    const int w = blockIdx.x * 256 + threadIdx.x;
    const int4* p = reinterpret_cast<const int4*>(adj) + (size_t)w * 8;
    unsigned bits = 0;
#pragma unroll
    for (int k = 0; k < 8; k++) {
        int4 v = p[k];
        bits |= (unsigned)(v.x != 0) << (k * 4 + 0);
        bits |= (unsigned)(v.y != 0) << (k * 4 + 1);
        bits |= (unsigned)(v.z != 0) << (k * 4 + 2);
        bits |= (unsigned)(v.w != 0) << (k * 4 + 3);
    }
    g_adjbits[w] = bits;
}

// ---------------- Kernel B: e1/e2 + per-(bh,quarter) maxes -------------------
// grid (64, 4), block 256: one n per thread.
__global__ __launch_bounds__(256) void calc_ec_k(const float* __restrict__ a) {
    const int bh = blockIdx.x;
    const int q  = blockIdx.y;
    const int h  = bh & 7;
    const int b  = bh >> 3;
    const int t  = threadIdx.x;
    const int n  = q * 256 + t;

    __shared__ __align__(16) float sa[64];
    __shared__ float sm1[8], sm2[8];
    if (t < 16)
        reinterpret_cast<float4*>(sa)[t] = reinterpret_cast<const float4*>(a + h * 64)[t];
    __syncthreads();

    const float* wp = g_Wh + ((size_t)b * 1024 + n) * 256 + h * 32;
    float e1 = 0.f, e2 = 0.f;
#pragma unroll
    for (int k4 = 0; k4 < 8; k4++) {
        float4 v = reinterpret_cast<const float4*>(wp)[k4];
        e1 += v.x * sa[k4 * 4 + 0] + v.y * sa[k4 * 4 + 1]
            + v.z * sa[k4 * 4 + 2] + v.w * sa[k4 * 4 + 3];
        e2 += v.x * sa[32 + k4 * 4 + 0] + v.y * sa[32 + k4 * 4 + 1]
            + v.z * sa[32 + k4 * 4 + 2] + v.w * sa[32 + k4 * 4 + 3];
    }
    g_e1[bh * 1024 + n] = e1;
    g_e2[bh * 1024 + n] = e2;

    float m1 = e1, m2 = e2;
#pragma unroll
    for (int off = 16; off; off >>= 1) {
        m1 = fmaxf(m1, __shfl_xor_sync(0xffffffffu, m1, off));
        m2 = fmaxf(m2, __shfl_xor_sync(0xffffffffu, m2, off));
    }
    if ((t & 31) == 0) { sm1[t >> 5] = m1; sm2[t >> 5] = m2; }
    __syncthreads();
    if (t < 32) {
        m1 = (t < 8) ? sm1[t] : -1e30f;
        m2 = (t < 8) ? sm2[t] : -1e30f;
#pragma unroll
        for (int off = 4; off; off >>= 1) {
            m1 = fmaxf(m1, __shfl_xor_sync(0xffffffffu, m1, off));
            m2 = fmaxf(m2, __shfl_xor_sync(0xffffffffu, m2, off));
        }
        if (t == 0) { g_M1[bh * 4 + q] = m1; g_M2[bh * 4 + q] = m2; }
    }
}

// ---------------- Kernel D: HMMA fused softmax + attn@Wh ---------------------
// Grid (8 i-tiles, 64 bh), 256 threads = 8 warps. Warp w owns rows w*16..+15.
// P computed directly in A-fragment layout. B staged in a depth-4 cp.async ring
// with ONE __syncthreads per chunk. B-fragments load as single LDS.64 thanks to
// the j-interleaved WhT layout.
__global__ __launch_bounds__(256, 2) void gat_mma_k(const float* __restrict__ bias,
                                                    float* __restrict__ out) {
    __shared__ __align__(16) __nv_bfloat16 sB[4][2][32][72];  // [slot][hi/lo][d][j]

    const int t    = threadIdx.x;
    const int w    = t >> 5;
    const int lane = t & 31;
    const int bh   = blockIdx.y;
    const int b    = bh >> 3, h = bh & 7;
    const int i0   = blockIdx.x * 128;

    const int r0 = lane >> 2;
    const int c0 = (lane & 3) * 2;

    // softmax shift from per-quarter maxes
    float C;
    {
        const float4 m1 = *reinterpret_cast<const float4*>(g_M1 + bh * 4);
        const float4 m2 = *reinterpret_cast<const float4*>(g_M2 + bh * 4);
        float a1 = fmaxf(fmaxf(m1.x, m1.y), fmaxf(m1.z, m1.w));
        float a2 = fmaxf(fmaxf(m2.x, m2.y), fmaxf(m2.z, m2.w));
        float s = a1 + a2;
        C = fmaxf(s, 0.2f * s);
    }

    const int   row0 = w * 16 + r0;
    const float K1 = 1.44269504f, K2 = 0.2f * 1.44269504f;
    const float e1_0 = g_e1[bh * 1024 + i0 + row0];
    const float e1_1 = g_e1[bh * 1024 + i0 + row0 + 8];
    const float c1_0 = e1_0 * K1 - C * K1, c2_0 = e1_0 * K2 - C * K1;
    const float c1_1 = e1_1 * K1 - C * K1, c2_1 = e1_1 * K2 - C * K1;

    const unsigned* __restrict__ mrow0 = g_adjbits + (size_t)(b * 1024 + i0 + row0) * 32;
    const unsigned* __restrict__ mrow1 = mrow0 + 8 * 32;
    const float* __restrict__ e2B = g_e2 + bh * 1024;

    // cp.async mapping: thread t stages d = t>>3, 8 j's at (t&7)*8
    const int cpd = t >> 3, cpj = (t & 7) * 8;
    const __nv_bfloat16* bsrc_hi = g_WhT_hi + (size_t)bh * 32768 + cpd * 1024 + cpj;
    const __nv_bfloat16* bsrc_lo = g_WhT_lo + (size_t)bh * 32768 + cpd * 1024 + cpj;
#define CP_B(C_)                                                              \
    {                                                                         \
        int sl = (C_) & 3;                                                    \
        cp16(s2u(&sB[sl][0][cpd][cpj]), bsrc_hi + (C_) * 64);                 \
        cp16(s2u(&sB[sl][1][cpd][cpj]), bsrc_lo + (C_) * 64);                 \
    }
    CP_B(0) cp_commit();
    CP_B(1) cp_commit();
    CP_B(2) cp_commit();

    float acc[4][4];
#pragma unroll
    for (int nt = 0; nt < 4; nt++)
#pragma unroll
        for (int q = 0; q < 4; q++) acc[nt][q] = 0.f;
    float den0 = 0.f, den1 = 0.f;

    for (int c = 0; c < 16; c++) {
        cp_wait<2>();                // group c landed (this thread)
        __syncthreads();             // visibility + everyone done with c-1
        if (c < 13) CP_B(c + 3)      // slot (c+3)&3 == (c-1)&3: safe past barrier
        cp_commit();
        const int sl = c & 3;

        const unsigned m0a = mrow0[2 * c], m0b = mrow0[2 * c + 1];
        const unsigned m1a = mrow1[2 * c], m1b = mrow1[2 * c + 1];

#pragma unroll
        for (int kt = 0; kt < 4; kt++) {
            const int jb = c * 64 + kt * 16;
            float2 eA = *reinterpret_cast<const float2*>(e2B + jb + c0);
            float2 eB = *reinterpret_cast<const float2*>(e2B + jb + c0 + 8);
            const int sh = ((kt & 1) * 16) + c0;
            const unsigned bits0 = ((kt >> 1) ? m0b : m0a) >> sh;
            const unsigned bits1 = ((kt >> 1) ? m1b : m1a) >> sh;

#define PP(DST, CONV1, CONV2, EV, BITS, POS)                                  \
            float DST;                                                        \
            {                                                                 \
                float s1 = fmaf((EV), K1, CONV1);                             \
                float s2 = fmaf((EV), K2, CONV2);                             \
                float e  = ex2f(fmaxf(s1, s2));                               \
                DST = (((BITS) >> (POS)) & 1u) ? e : 0.f;                     \
            }
            PP(p00, c1_0, c2_0, eA.x, bits0, 0)
            PP(p01, c1_0, c2_0, eA.y, bits0, 1)
            PP(p08, c1_0, c2_0, eB.x, bits0, 8)
            PP(p09, c1_0, c2_0, eB.y, bits0, 9)
            PP(p10, c1_1, c2_1, eA.x, bits1, 0)
            PP(p11, c1_1, c2_1, eA.y, bits1, 1)
            PP(p18, c1_1, c2_1, eB.x, bits1, 8)
            PP(p19, c1_1, c2_1, eB.y, bits1, 9)
#undef PP
            den0 += (p00 + p01) + (p08 + p09);
            den1 += (p10 + p11) + (p18 + p19);

            uint32_t ah0 = cvt2bf(p01, p00);
            uint32_t ah1 = cvt2bf(p11, p10);
            uint32_t ah2 = cvt2bf(p09, p08);
            uint32_t ah3 = cvt2bf(p19, p18);
            uint32_t al0 = cvt2bf(p01 - __uint_as_float(ah0 & 0xffff0000u),
                                  p00 - __uint_as_float(ah0 << 16));
            uint32_t al1 = cvt2bf(p11 - __uint_as_float(ah1 & 0xffff0000u),
                                  p10 - __uint_as_float(ah1 << 16));
            uint32_t al2 = cvt2bf(p09 - __uint_as_float(ah2 & 0xffff0000u),
                                  p08 - __uint_as_float(ah2 << 16));
            uint32_t al3 = cvt2bf(p19 - __uint_as_float(ah3 & 0xffff0000u),
                                  p18 - __uint_as_float(ah3 << 16));

#pragma unroll
            for (int nt = 0; nt < 4; nt++) {
                // interleaved layout: (b0,b1) = one 8-byte LDS
                uint2 bhp = *reinterpret_cast<const uint2*>(
                    &sB[sl][0][nt * 8 + r0][kt * 16 + c0 * 2]);
                uint2 blp = *reinterpret_cast<const uint2*>(
                    &sB[sl][1][nt * 8 + r0][kt * 16 + c0 * 2]);
                mma16816(acc[nt], ah0, ah1, ah2, ah3, bhp.x, bhp.y);
                mma16816(acc[nt], ah0, ah1, ah2, ah3, blp.x, blp.y);
                mma16816(acc[nt], al0, al1, al2, al3, bhp.x, bhp.y);
            }
        }
    }
#undef CP_B

    den0 += __shfl_xor_sync(0xffffffffu, den0, 1);
    den0 += __shfl_xor_sync(0xffffffffu, den0, 2);
    den1 += __shfl_xor_sync(0xffffffffu, den1, 1);
    den1 += __shfl_xor_sync(0xffffffffu, den1, 2);
    const float rd0 = 1.0f / den0;
    const float rd1 = 1.0f / den1;

    float* o0 = out + ((size_t)(b * 1024 + i0 + row0)) * 256 + h * 32;
    float* o1 = o0 + 8 * 256;
#pragma unroll
    for (int nt = 0; nt < 4; nt++) {
        const int dcol = nt * 8 + c0;
        float2 bi = *reinterpret_cast<const float2*>(bias + h * 32 + dcol);
        float2 v0, v1;
        v0.x = fmaxf(acc[nt][0] * rd0 + bi.x, 0.f);
        v0.y = fmaxf(acc[nt][1] * rd0 + bi.y, 0.f);
        v1.x = fmaxf(acc[nt][2] * rd1 + bi.x, 0.f);
        v1.y = fmaxf(acc[nt][3] * rd1 + bi.y, 0.f);
        *reinterpret_cast<float2*>(o0 + dcol) = v0;
        *reinterpret_cast<float2*>(o1 + dcol) = v1;
    }
}

// ---------------- launcher ---------------------------------------------------
extern "C" void kernel_launch(void* const* d_in, const int* in_sizes, int n_in,
                              void* d_out, int out_size) {
    const float* nf   = (const float*)d_in[0];   // (8,1024,256)
    const int*   adj  = (const int*)d_in[1];     // (8,1024,1024)
    const float* W    = (const float*)d_in[2];   // (8,256,32)
    const float* a    = (const float*)d_in[3];   // (8,64)
    const float* bias = (const float*)d_in[4];   // (256,)
    float*       out  = (float*)d_out;           // (8,1024,256)

    bitpack_k<<<1024, 256>>>(adj);
    gemm_wh_k<<<dim3(128, 4), 256>>>(nf, W);
    calc_ec_k<<<dim3(64, 4), 256>>>(a);
    gat_mma_k<<<dim3(8, 64), 256>>>(bias, out);
}

// round 10
// speedup vs baseline: 2.1885x; 1.0268x over previous
#include <cuda_runtime.h>
#include <cuda_bf16.h>
#include <cstdint>
#include <cstddef>

typedef unsigned long long ull;

// ---------------- scratch (static device globals; no runtime alloc) ----------
__device__ __align__(16) float g_e1[65536];            // [(b*8+h)*1024 + n]
__device__ __align__(16) float g_e2[65536];
__device__ __align__(16) unsigned g_M1u[64];           // per-bh max e1 (encoded)
__device__ __align__(16) unsigned g_M2u[64];           // per-bh max e2 (encoded)
__device__ __align__(16) unsigned g_adjbits[8 * 1024 * 32];          // 1 MB
// k-pair-interleaved bf16 splits (within 16-groups: pairs (0,1),(8,9),(2,3),(10,11),...)
__device__ __align__(16) __nv_bfloat16 g_Xh[8192 * 256];             // [m][k]
__device__ __align__(16) __nv_bfloat16 g_Xl[8192 * 256];
__device__ __align__(16) __nv_bfloat16 g_WT_hi[256 * 256];           // [h*32+d][k]
__device__ __align__(16) __nv_bfloat16 g_WT_lo[256 * 256];
__device__ __align__(16) __nv_bfloat16 g_WhT_hi[64 * 32 * 1024];     // [bh][d][n]
__device__ __align__(16) __nv_bfloat16 g_WhT_lo[64 * 32 * 1024];

// ---------------- small PTX helpers ------------------------------------------
__device__ __forceinline__ uint32_t s2u(const void* p) {
    return (uint32_t)__cvta_generic_to_shared(p);
}
__device__ __forceinline__ void cp16(uint32_t dst, const void* src) {
    asm volatile("cp.async.cg.shared.global [%0], [%1], 16;" :: "r"(dst), "l"(src));
}
__device__ __forceinline__ void cp_commit() { asm volatile("cp.async.commit_group;"); }
template <int N> __device__ __forceinline__ void cp_wait() {
    asm volatile("cp.async.wait_group %0;" :: "n"(N));
}
__device__ __forceinline__ float ex2f(float x) {
    float r; asm("ex2.approx.ftz.f32 %0, %1;" : "=f"(r) : "f"(x)); return r;
}
// pack: low half = bf16(l), high half = bf16(h)
__device__ __forceinline__ uint32_t cvt2bf(float h, float l) {
    uint32_t r; asm("cvt.rn.bf16x2.f32 %0, %1, %2;" : "=r"(r) : "f"(h), "f"(l)); return r;
}
__device__ __forceinline__ uint2 lds64(uint32_t a) {
    uint2 v;
    asm volatile("ld.shared.v2.b32 {%0,%1}, [%2];" : "=r"(v.x), "=r"(v.y) : "r"(a));
    return v;
}
// D(16x8,f32) += A(16x16,bf16,row) * B(16x8,bf16,col)
__device__ __forceinline__ void mma16816(float* d,
                                         uint32_t a0, uint32_t a1, uint32_t a2, uint32_t a3,
                                         uint32_t b0, uint32_t b1) {
    asm volatile(
        "mma.sync.aligned.m16n8k16.row.col.f32.bf16.bf16.f32 "
        "{%0,%1,%2,%3}, {%4,%5,%6,%7}, {%8,%9}, {%0,%1,%2,%3};"
        : "+f"(d[0]), "+f"(d[1]), "+f"(d[2]), "+f"(d[3])
        : "r"(a0), "r"(a1), "r"(a2), "r"(a3), "r"(b0), "r"(b1));
}
// monotone float<->uint encoding for atomicMax over signed floats
__device__ __forceinline__ unsigned encf(float f) {
    unsigned u = __float_as_uint(f);
    return (u & 0x80000000u) ? ~u : (u | 0x80000000u);
}
__device__ __forceinline__ float decf(unsigned k) {
    unsigned u = (k & 0x80000000u) ? (k ^ 0x80000000u) : ~k;
    return __uint_as_float(u);
}
// split 16 fp32 -> 8 hi + 8 lo bf16x2 words, k-pair interleaved
__device__ __forceinline__ void split16(const float* v, uint32_t* H, uint32_t* L) {
    const int perm[8] = {0, 8, 2, 10, 4, 12, 6, 14};
#pragma unroll
    for (int m = 0; m < 8; m++) {
        float f0 = v[perm[m]], f1 = v[perm[m] + 1];
        uint32_t hw = cvt2bf(f1, f0);
        float r0 = f0 - __uint_as_float(hw << 16);
        float r1 = f1 - __uint_as_float(hw & 0xffff0000u);
        H[m] = hw;
        L[m] = cvt2bf(r1, r0);
    }
}

// ---------------- Kernel P1: split X fp32 -> bf16 hi/lo (interleaved) --------
__global__ __launch_bounds__(256) void split_x_k(const float* __restrict__ X) {
    const int g = blockIdx.x * 256 + threadIdx.x;      // 131072 16-float groups
    float v[16];
    const float4* s4 = reinterpret_cast<const float4*>(X + (size_t)g * 16);
#pragma unroll
    for (int q = 0; q < 4; q++) {
        float4 f = s4[q];
        v[q * 4 + 0] = f.x; v[q * 4 + 1] = f.y;
        v[q * 4 + 2] = f.z; v[q * 4 + 3] = f.w;
    }
    uint32_t H[8], L[8];
    split16(v, H, L);
    uint4* dh = reinterpret_cast<uint4*>(g_Xh + (size_t)g * 16);
    uint4* dl = reinterpret_cast<uint4*>(g_Xl + (size_t)g * 16);
    dh[0] = make_uint4(H[0], H[1], H[2], H[3]);
    dh[1] = make_uint4(H[4], H[5], H[6], H[7]);
    dl[0] = make_uint4(L[0], L[1], L[2], L[3]);
    dl[1] = make_uint4(L[4], L[5], L[6], L[7]);
}

// ---------------- Kernel P2: split/transpose W + init max keys ---------------
__global__ __launch_bounds__(256) void split_w_k(const float* __restrict__ W) {
    const int t = threadIdx.x;
    if (blockIdx.x == 0 && t < 64) { g_M1u[t] = 0u; g_M2u[t] = 0u; }
    const int task = blockIdx.x * 256 + t;             // 4096 tasks
    const int h   = task >> 9;
    const int d   = (task >> 4) & 31;
    const int grp = task & 15;
    const float* wp = W + (size_t)h * 8192 + (size_t)grp * 16 * 32 + d;
    float v[16];
#pragma unroll
    for (int k = 0; k < 16; k++) v[k] = wp[k * 32];
    uint32_t H[8], L[8];
    split16(v, H, L);
    const size_t off = (size_t)(h * 32 + d) * 256 + grp * 16;
    uint4* dh = reinterpret_cast<uint4*>(g_WT_hi + off);
    uint4* dl = reinterpret_cast<uint4*>(g_WT_lo + off);
    dh[0] = make_uint4(H[0], H[1], H[2], H[3]);
    dh[1] = make_uint4(H[4], H[5], H[6], H[7]);
    dl[0] = make_uint4(L[0], L[1], L[2], L[3]);
    dl[1] = make_uint4(L[4], L[5], L[6], L[7]);
}

// ---------------- Kernel A2: bitpack adjacency -------------------------------
__global__ __launch_bounds__(256) void bitpack_k(const int* __restrict__ adj) {
    const int w = blockIdx.x * 256 + threadIdx.x;
    const int4* p = reinterpret_cast<const int4*>(adj) + (size_t)w * 8;
    unsigned bits = 0;
#pragma unroll
    for (int k = 0; k < 8; k++) {
        int4 v = p[k];
        bits |= (unsigned)(v.x != 0) << (k * 4 + 0);
        bits |= (unsigned)(v.y != 0) << (k * 4 + 1);
        bits |= (unsigned)(v.z != 0) << (k * 4 + 2);
        bits |= (unsigned)(v.w != 0) << (k * 4 + 3);
    }
    g_adjbits[w] = bits;
}

// ---------------- Kernel G: HMMA Wh GEMM + fused WhT/e1/e2/max epilogue ------
// Grid (128 m-tiles, 4 c-tiles), 256 threads = 8 warps (4 m-groups x 2 n-groups).
// A (X hi/lo) via cp.async depth-4 ring of k32 stages; B (WT hi/lo) via LDG (L1/L2).
__global__ __launch_bounds__(256) void gemm_mma_k(const float* __restrict__ av) {
    __shared__ __align__(16) char sm[40960];   // 4 slots x [2 hl][64 m][40 k] bf16
    __shared__ __align__(16) float sa[128];    // a-vectors for the 2 heads

    const int t    = threadIdx.x;
    const int lane = t & 31;
    const int w    = t >> 5;
    const int bm   = blockIdx.x;
    const int bn   = blockIdx.y;
    const int m0   = bm * 64;
    const int wm   = w >> 1;
    const int wc   = w & 1;
    const int r0   = lane >> 2;
    const int c0   = (lane & 3) * 2;

    if (t < 32)
        reinterpret_cast<float4*>(sa)[t] =
            reinterpret_cast<const float4*>(av + bn * 128)[t];

    // A cp.async mapping: thread -> (row, 16B seg)
    const int cprow = t >> 2, cpseg = t & 3;
    const __nv_bfloat16* xh = g_Xh + (size_t)(m0 + cprow) * 256 + cpseg * 8;
    const __nv_bfloat16* xl = g_Xl + (size_t)(m0 + cprow) * 256 + cpseg * 8;
    const uint32_t adst = s2u(sm) + cprow * 80 + cpseg * 16;
#define CP_A(S)                                                               \
    {                                                                         \
        uint32_t sl = ((uint32_t)(S) & 3u) * 10240u;                          \
        cp16(adst + sl,        xh + (S) * 32);                                \
        cp16(adst + sl + 5120, xl + (S) * 32);                                \
    }
    CP_A(0) cp_commit();
    CP_A(1) cp_commit();
    CP_A(2) cp_commit();

    // B base pointers (ntile nt adds nt*8*256)
    const __nv_bfloat16* wthB = g_WT_hi + (size_t)(bn * 64 + wc * 32 + r0) * 256 + 2 * c0;
    const __nv_bfloat16* wtlB = g_WT_lo + (size_t)(bn * 64 + wc * 32 + r0) * 256 + 2 * c0;

    float acc[4][4];
#pragma unroll
    for (int nt = 0; nt < 4; nt++)
#pragma unroll
        for (int q = 0; q < 4; q++) acc[nt][q] = 0.f;

    const uint32_t abase = s2u(sm) + (wm * 16 + r0) * 80 + c0 * 4;

    for (int s = 0; s < 8; s++) {
        cp_wait<2>();
        __syncthreads();
        if (s < 5) CP_A(s + 3)
        cp_commit();
        const uint32_t ab = abase + ((uint32_t)s & 3u) * 10240u;
#pragma unroll
        for (int ck = 0; ck < 2; ck++) {
            uint2 Ah0 = lds64(ab + ck * 32);             // (a0, a2) hi, row r0
            uint2 Ah1 = lds64(ab + ck * 32 + 8 * 80);    // (a1, a3) hi, row r0+8
            uint2 Al0 = lds64(ab + 5120 + ck * 32);
            uint2 Al1 = lds64(ab + 5120 + ck * 32 + 8 * 80);
            const int kk = s * 32 + ck * 16;
#pragma unroll
            for (int nt = 0; nt < 4; nt++) {
                uint2 Bh = *reinterpret_cast<const uint2*>(wthB + nt * 2048 + kk);
                uint2 Bl = *reinterpret_cast<const uint2*>(wtlB + nt * 2048 + kk);
                mma16816(acc[nt], Ah0.x, Ah1.x, Ah0.y, Ah1.y, Bh.x, Bh.y);
                mma16816(acc[nt], Ah0.x, Ah1.x, Ah0.y, Ah1.y, Bl.x, Bl.y);
                mma16816(acc[nt], Al0.x, Al1.x, Al0.y, Al1.y, Bh.x, Bh.y);
            }
        }
    }
#undef CP_A
    __syncthreads();

    // ---- epilogue: stage Wh tile as sT[c][m] fp32 (aliases A ring) ----
    float* sT = reinterpret_cast<float*>(sm);            // [64][68]
#pragma unroll
    for (int nt = 0; nt < 4; nt++) {
        const int c = wc * 32 + nt * 8 + c0;
        const int m = wm * 16 + r0;
        sT[(c + 0) * 68 + m]     = acc[nt][0];
        sT[(c + 1) * 68 + m]     = acc[nt][1];
        sT[(c + 0) * 68 + m + 8] = acc[nt][2];
        sT[(c + 1) * 68 + m + 8] = acc[nt][3];
    }
    __syncthreads();

    // (a) transposed bf16 hi/lo WhT write (same layout gat_mma reads)
    {
        const int c   = t >> 2;
        const int seg = t & 3;
        const int b   = bm >> 4;
        const int n0  = (bm & 15) * 64 + seg * 16;
        const int h   = 2 * bn + (c >> 5);
        const int d   = c & 31;
        float v[16];
        const float4* rp = reinterpret_cast<const float4*>(&sT[c * 68 + seg * 16]);
#pragma unroll
        for (int q = 0; q < 4; q++) {
            float4 f = rp[q];
            v[q * 4 + 0] = f.x; v[q * 4 + 1] = f.y;
            v[q * 4 + 2] = f.z; v[q * 4 + 3] = f.w;
        }
        uint32_t H[8], L[8];
        split16(v, H, L);
        const size_t off = (size_t)(b * 8 + h) * 32768 + (size_t)d * 1024 + n0;
        uint4* dh = reinterpret_cast<uint4*>(g_WhT_hi + off);
        uint4* dl = reinterpret_cast<uint4*>(g_WhT_lo + off);
        dh[0] = make_uint4(H[0], H[1], H[2], H[3]);
        dh[1] = make_uint4(H[4], H[5], H[6], H[7]);
        dl[0] = make_uint4(L[0], L[1], L[2], L[3]);
        dl[1] = make_uint4(L[4], L[5], L[6], L[7]);
    }

    // (b) e1/e2 + per-bh max atomics
    if (t < 128) {
        const int hh = t >> 6, r = t & 63;
        float e1 = 0.f, e2 = 0.f;
#pragma unroll
        for (int d = 0; d < 32; d++) {
            float v = sT[(hh * 32 + d) * 68 + r];
            e1 = fmaf(v, sa[hh * 64 + d], e1);
            e2 = fmaf(v, sa[hh * 64 + 32 + d], e2);
        }
        const int m  = m0 + r;
        const int b  = m >> 10, n = m & 1023;
        const int bh = b * 8 + bn * 2 + hh;
        g_e1[bh * 1024 + n] = e1;
        g_e2[bh * 1024 + n] = e2;

        float m1 = e1, m2 = e2;
#pragma unroll
        for (int off = 16; off; off >>= 1) {
            m1 = fmaxf(m1, __shfl_xor_sync(0xffffffffu, m1, off));
            m2 = fmaxf(m2, __shfl_xor_sync(0xffffffffu, m2, off));
        }
        if (lane == 0) {
            atomicMax(&g_M1u[bh], encf(m1));
            atomicMax(&g_M2u[bh], encf(m2));
        }
    }
}

// ---------------- Kernel D: HMMA fused softmax + attn@Wh ---------------------
__global__ __launch_bounds__(256, 2) void gat_mma_k(const float* __restrict__ bias,
                                                    float* __restrict__ out) {
    __shared__ __align__(16) __nv_bfloat16 sB[4][2][32][72];  // [slot][hi/lo][d][j]

    const int t    = threadIdx.x;
    const int w    = t >> 5;
    const int lane = t & 31;
    const int bh   = blockIdx.y;
    const int b    = bh >> 3, h = bh & 7;
    const int i0   = blockIdx.x * 128;

    const int r0 = lane >> 2;
    const int c0 = (lane & 3) * 2;

    float C;
    {
        float a1 = decf(g_M1u[bh]);
        float a2 = decf(g_M2u[bh]);
        float s = a1 + a2;
        C = fmaxf(s, 0.2f * s);
    }

    const int   row0 = w * 16 + r0;
    const float K1 = 1.44269504f, K2 = 0.2f * 1.44269504f;
    const float e1_0 = g_e1[bh * 1024 + i0 + row0];
    const float e1_1 = g_e1[bh * 1024 + i0 + row0 + 8];
    const float c1_0 = e1_0 * K1 - C * K1, c2_0 = e1_0 * K2 - C * K1;
    const float c1_1 = e1_1 * K1 - C * K1, c2_1 = e1_1 * K2 - C * K1;

    const unsigned* __restrict__ mrow0 = g_adjbits + (size_t)(b * 1024 + i0 + row0) * 32;
    const unsigned* __restrict__ mrow1 = mrow0 + 8 * 32;
    const float* __restrict__ e2B = g_e2 + bh * 1024;

    const int cpd = t >> 3, cpj = (t & 7) * 8;
    const __nv_bfloat16* bsrc_hi = g_WhT_hi + (size_t)bh * 32768 + cpd * 1024 + cpj;
    const __nv_bfloat16* bsrc_lo = g_WhT_lo + (size_t)bh * 32768 + cpd * 1024 + cpj;
#define CP_B(C_)                                                              \
    {                                                                         \
        int sl = (C_) & 3;                                                    \
        cp16(s2u(&sB[sl][0][cpd][cpj]), bsrc_hi + (C_) * 64);                 \
        cp16(s2u(&sB[sl][1][cpd][cpj]), bsrc_lo + (C_) * 64);                 \
    }
    CP_B(0) cp_commit();
    CP_B(1) cp_commit();
    CP_B(2) cp_commit();

    float acc[4][4];
#pragma unroll
    for (int nt = 0; nt < 4; nt++)
#pragma unroll
        for (int q = 0; q < 4; q++) acc[nt][q] = 0.f;
    float den0 = 0.f, den1 = 0.f;

    for (int c = 0; c < 16; c++) {
        cp_wait<2>();
        __syncthreads();
        if (c < 13) CP_B(c + 3)
        cp_commit();
        const int sl = c & 3;

        const unsigned m0a = mrow0[2 * c], m0b = mrow0[2 * c + 1];
        const unsigned m1a = mrow1[2 * c], m1b = mrow1[2 * c + 1];

#pragma unroll
        for (int kt = 0; kt < 4; kt++) {
            const int jb = c * 64 + kt * 16;
            float2 eA = *reinterpret_cast<const float2*>(e2B + jb + c0);
            float2 eB = *reinterpret_cast<const float2*>(e2B + jb + c0 + 8);
            const int sh = ((kt & 1) * 16) + c0;
            const unsigned bits0 = ((kt >> 1) ? m0b : m0a) >> sh;
            const unsigned bits1 = ((kt >> 1) ? m1b : m1a) >> sh;

#define PP(DST, CONV1, CONV2, EV, BITS, POS)                                  \
            float DST;                                                        \
            {                                                                 \
                float s1 = fmaf((EV), K1, CONV1);                             \
                float s2 = fmaf((EV), K2, CONV2);                             \
                float e  = ex2f(fmaxf(s1, s2));                               \
                DST = (((BITS) >> (POS)) & 1u) ? e : 0.f;                     \
            }
            PP(p00, c1_0, c2_0, eA.x, bits0, 0)
            PP(p01, c1_0, c2_0, eA.y, bits0, 1)
            PP(p08, c1_0, c2_0, eB.x, bits0, 8)
            PP(p09, c1_0, c2_0, eB.y, bits0, 9)
            PP(p10, c1_1, c2_1, eA.x, bits1, 0)
            PP(p11, c1_1, c2_1, eA.y, bits1, 1)
            PP(p18, c1_1, c2_1, eB.x, bits1, 8)
            PP(p19, c1_1, c2_1, eB.y, bits1, 9)
#undef PP
            den0 += (p00 + p01) + (p08 + p09);
            den1 += (p10 + p11) + (p18 + p19);

            uint32_t ah0 = cvt2bf(p01, p00);
            uint32_t ah1 = cvt2bf(p11, p10);
            uint32_t ah2 = cvt2bf(p09, p08);
            uint32_t ah3 = cvt2bf(p19, p18);
            uint32_t al0 = cvt2bf(p01 - __uint_as_float(ah0 & 0xffff0000u),
                                  p00 - __uint_as_float(ah0 << 16));
            uint32_t al1 = cvt2bf(p11 - __uint_as_float(ah1 & 0xffff0000u),
                                  p10 - __uint_as_float(ah1 << 16));
            uint32_t al2 = cvt2bf(p09 - __uint_as_float(ah2 & 0xffff0000u),
                                  p08 - __uint_as_float(ah2 << 16));
            uint32_t al3 = cvt2bf(p19 - __uint_as_float(ah3 & 0xffff0000u),
                                  p18 - __uint_as_float(ah3 << 16));

#pragma unroll
            for (int nt = 0; nt < 4; nt++) {
                uint2 bhp = *reinterpret_cast<const uint2*>(
                    &sB[sl][0][nt * 8 + r0][kt * 16 + c0 * 2]);
                uint2 blp = *reinterpret_cast<const uint2*>(
                    &sB[sl][1][nt * 8 + r0][kt * 16 + c0 * 2]);
                mma16816(acc[nt], ah0, ah1, ah2, ah3, bhp.x, bhp.y);
                mma16816(acc[nt], ah0, ah1, ah2, ah3, blp.x, blp.y);
                mma16816(acc[nt], al0, al1, al2, al3, bhp.x, bhp.y);
            }
        }
    }
#undef CP_B

    den0 += __shfl_xor_sync(0xffffffffu, den0, 1);
    den0 += __shfl_xor_sync(0xffffffffu, den0, 2);
    den1 += __shfl_xor_sync(0xffffffffu, den1, 1);
    den1 += __shfl_xor_sync(0xffffffffu, den1, 2);
    const float rd0 = 1.0f / den0;
    const float rd1 = 1.0f / den1;

    float* o0 = out + ((size_t)(b * 1024 + i0 + row0)) * 256 + h * 32;
    float* o1 = o0 + 8 * 256;
#pragma unroll
    for (int nt = 0; nt < 4; nt++) {
        const int dcol = nt * 8 + c0;
        float2 bi = *reinterpret_cast<const float2*>(bias + h * 32 + dcol);
        float2 v0, v1;
        v0.x = fmaxf(acc[nt][0] * rd0 + bi.x, 0.f);
        v0.y = fmaxf(acc[nt][1] * rd0 + bi.y, 0.f);
        v1.x = fmaxf(acc[nt][2] * rd1 + bi.x, 0.f);
        v1.y = fmaxf(acc[nt][3] * rd1 + bi.y, 0.f);
        *reinterpret_cast<float2*>(o0 + dcol) = v0;
        *reinterpret_cast<float2*>(o1 + dcol) = v1;
    }
}

// ---------------- launcher ---------------------------------------------------
extern "C" void kernel_launch(void* const* d_in, const int* in_sizes, int n_in,
                              void* d_out, int out_size) {
    const float* nf   = (const float*)d_in[0];   // (8,1024,256)
    const int*   adj  = (const int*)d_in[1];     // (8,1024,1024)
    const float* W    = (const float*)d_in[2];   // (8,256,32)
    const float* a    = (const float*)d_in[3];   // (8,64)
    const float* bias = (const float*)d_in[4];   // (256,)
    float*       out  = (float*)d_out;           // (8,1024,256)

    split_x_k<<<512, 256>>>(nf);
    split_w_k<<<16, 256>>>(W);
    bitpack_k<<<1024, 256>>>(adj);
    gemm_mma_k<<<dim3(128, 4), 256>>>(a);
    gat_mma_k<<<dim3(8, 64), 256>>>(bias, out);
}

// round 12
// speedup vs baseline: 2.4133x; 1.1027x over previous
#include <cuda_runtime.h>
#include <cuda_bf16.h>
#include <cstdint>
#include <cstddef>

typedef unsigned long long ull;

// ---------------- scratch (static device globals; no runtime alloc) ----------
__device__ __align__(16) float g_e1[65536];            // [(b*8+h)*1024 + n]
__device__ __align__(16) float g_e2[65536];
__device__ __align__(16) float g_E2f[65536 * 2];       // per-j factor pair (Bp,Bm)
__device__ __align__(16) unsigned g_M1u[64];           // per-bh max e1 (encoded)
__device__ __align__(16) unsigned g_M2u[64];           // per-bh max e2 (encoded)
__device__ __align__(16) unsigned g_adjbits[8 * 1024 * 32];          // 1 MB
// k-pair-interleaved bf16 splits (within 16-groups: pairs (0,1),(8,9),(2,3),(10,11),...)
__device__ __align__(16) __nv_bfloat16 g_Xh[8192 * 256];             // [m][k]
__device__ __align__(16) __nv_bfloat16 g_Xl[8192 * 256];
__device__ __align__(16) __nv_bfloat16 g_WT_hi[256 * 256];           // [h*32+d][k]
__device__ __align__(16) __nv_bfloat16 g_WT_lo[256 * 256];
__device__ __align__(16) __nv_bfloat16 g_WhT_hi[64 * 32 * 1024];     // [bh][d][n]
__device__ __align__(16) __nv_bfloat16 g_WhT_lo[64 * 32 * 1024];

// ---------------- small PTX helpers ------------------------------------------
__device__ __forceinline__ uint32_t s2u(const void* p) {
    return (uint32_t)__cvta_generic_to_shared(p);
}
__device__ __forceinline__ void cp16(uint32_t dst, const void* src) {
    asm volatile("cp.async.cg.shared.global [%0], [%1], 16;" :: "r"(dst), "l"(src));
}
__device__ __forceinline__ void cp_commit() { asm volatile("cp.async.commit_group;"); }
template <int N> __device__ __forceinline__ void cp_wait() {
    asm volatile("cp.async.wait_group %0;" :: "n"(N));
}
// pack: low half = bf16(l), high half = bf16(h)
__device__ __forceinline__ uint32_t cvt2bf(float h, float l) {
    uint32_t r; asm("cvt.rn.bf16x2.f32 %0, %1, %2;" : "=r"(r) : "f"(h), "f"(l)); return r;
}
__device__ __forceinline__ uint2 lds64(uint32_t a) {
    uint2 v;
    asm volatile("ld.shared.v2.b32 {%0,%1}, [%2];" : "=r"(v.x), "=r"(v.y) : "r"(a));
    return v;
}
// D(16x8,f32) += A(16x16,bf16,row) * B(16x8,bf16,col)
__device__ __forceinline__ void mma16816(float* d,
                                         uint32_t a0, uint32_t a1, uint32_t a2, uint32_t a3,
                                         uint32_t b0, uint32_t b1) {
    asm volatile(
        "mma.sync.aligned.m16n8k16.row.col.f32.bf16.bf16.f32 "
        "{%0,%1,%2,%3}, {%4,%5,%6,%7}, {%8,%9}, {%0,%1,%2,%3};"
        : "+f"(d[0]), "+f"(d[1]), "+f"(d[2]), "+f"(d[3])
        : "r"(a0), "r"(a1), "r"(a2), "r"(a3), "r"(b0), "r"(b1));
}
// monotone float<->uint encoding for atomicMax over signed floats
__device__ __forceinline__ unsigned encf(float f) {
    unsigned u = __float_as_uint(f);
    return (u & 0x80000000u) ? ~u : (u | 0x80000000u);
}
__device__ __forceinline__ float decf(unsigned k) {
    unsigned u = (k & 0x80000000u) ? (k ^ 0x80000000u) : ~k;
    return __uint_as_float(u);
}
// split 16 fp32 -> 8 hi + 8 lo bf16x2 words, k-pair interleaved
__device__ __forceinline__ void split16(const float* v, uint32_t* H, uint32_t* L) {
    const int perm[8] = {0, 8, 2, 10, 4, 12, 6, 14};
#pragma unroll
    for (int m = 0; m < 8; m++) {
        float f0 = v[perm[m]], f1 = v[perm[m] + 1];
        uint32_t hw = cvt2bf(f1, f0);
        float r0 = f0 - __uint_as_float(hw << 16);
        float r1 = f1 - __uint_as_float(hw & 0xffff0000u);
        H[m] = hw;
        L[m] = cvt2bf(r1, r0);
    }
}

// ---------------- Kernel P1: split X fp32 -> bf16 hi/lo (interleaved) --------
__global__ __launch_bounds__(256) void split_x_k(const float* __restrict__ X) {
    const int g = blockIdx.x * 256 + threadIdx.x;
    float v[16];
    const float4* s4 = reinterpret_cast<const float4*>(X + (size_t)g * 16);
#pragma unroll
    for (int q = 0; q < 4; q++) {
        float4 f = s4[q];
        v[q * 4 + 0] = f.x; v[q * 4 + 1] = f.y;
        v[q * 4 + 2] = f.z; v[q * 4 + 3] = f.w;
    }
    uint32_t H[8], L[8];
    split16(v, H, L);
    uint4* dh = reinterpret_cast<uint4*>(g_Xh + (size_t)g * 16);
    uint4* dl = reinterpret_cast<uint4*>(g_Xl + (size_t)g * 16);
    dh[0] = make_uint4(H[0], H[1], H[2], H[3]);
    dh[1] = make_uint4(H[4], H[5], H[6], H[7]);
    dl[0] = make_uint4(L[0], L[1], L[2], L[3]);
    dl[1] = make_uint4(L[4], L[5], L[6], L[7]);
}

// ---------------- Kernel P2: split/transpose W + init max keys ---------------
__global__ __launch_bounds__(256) void split_w_k(const float* __restrict__ W) {
    const int t = threadIdx.x;
    if (blockIdx.x == 0 && t < 64) { g_M1u[t] = 0u; g_M2u[t] = 0u; }
    const int task = blockIdx.x * 256 + t;
    const int h   = task >> 9;
    const int d   = (task >> 4) & 31;
    const int grp = task & 15;
    const float* wp = W + (size_t)h * 8192 + (size_t)grp * 16 * 32 + d;
    float v[16];
#pragma unroll
    for (int k = 0; k < 16; k++) v[k] = wp[k * 32];
    uint32_t H[8], L[8];
    split16(v, H, L);
    const size_t off = (size_t)(h * 32 + d) * 256 + grp * 16;
    uint4* dh = reinterpret_cast<uint4*>(g_WT_hi + off);
    uint4* dl = reinterpret_cast<uint4*>(g_WT_lo + off);
    dh[0] = make_uint4(H[0], H[1], H[2], H[3]);
    dh[1] = make_uint4(H[4], H[5], H[6], H[7]);
    dl[0] = make_uint4(L[0], L[1], L[2], L[3]);
    dl[1] = make_uint4(L[4], L[5], L[6], L[7]);
}

// ---------------- Kernel A2: bitpack adjacency -------------------------------
__global__ __launch_bounds__(256) void bitpack_k(const int* __restrict__ adj) {
    const int w = blockIdx.x * 256 + threadIdx.x;
    const int4* p = reinterpret_cast<const int4*>(adj) + (size_t)w * 8;
    unsigned bits = 0;
#pragma unroll
    for (int k = 0; k < 8; k++) {
        int4 v = p[k];
        bits |= (unsigned)(v.x != 0) << (k * 4 + 0);
        bits |= (unsigned)(v.y != 0) << (k * 4 + 1);
        bits |= (unsigned)(v.z != 0) << (k * 4 + 2);
        bits |= (unsigned)(v.w != 0) << (k * 4 + 3);
    }
    g_adjbits[w] = bits;
}

// ---------------- Kernel G: HMMA Wh GEMM + fused WhT/e1/e2/max epilogue ------
// Dynamic smem: A ring (4 x 10240) + B planes (2 x 64 x 544B) + sa.
#define GB_OFF    40960
#define GB_PLANE  34816
#define GB_STRIDE 544
#define GSA_OFF   (GB_OFF + 2 * GB_PLANE)      // 110592
#define GSM_TOTAL (GSA_OFF + 512)              // 111104

__global__ __launch_bounds__(256) void gemm_mma_k(const float* __restrict__ av) {
    extern __shared__ __align__(16) char dsm[];
    float* sa = reinterpret_cast<float*>(dsm + GSA_OFF);

    const int t    = threadIdx.x;
    const int lane = t & 31;
    const int w    = t >> 5;
    const int bm   = blockIdx.x;
    const int bn   = blockIdx.y;
    const int m0   = bm * 64;
    const int wm   = w >> 1;
    const int wc   = w & 1;
    const int r0   = lane >> 2;
    const int c0   = (lane & 3) * 2;

    if (t < 32)
        reinterpret_cast<float4*>(sa)[t] =
            reinterpret_cast<const float4*>(av + bn * 128)[t];

    // ---- one-time B staging (group 0): 64 rows x 512B per plane ----
    {
        const int brow = t >> 2, bseg = t & 3;
        const uint32_t bdst = s2u(dsm) + GB_OFF + brow * GB_STRIDE;
        const __nv_bfloat16* bsh = g_WT_hi + (size_t)(bn * 64 + brow) * 256;
        const __nv_bfloat16* bsl = g_WT_lo + (size_t)(bn * 64 + brow) * 256;
#pragma unroll
        for (int q = 0; q < 8; q++) {
            const int seg = bseg + q * 4;
            cp16(bdst + seg * 16,            bsh + seg * 8);
            cp16(bdst + GB_PLANE + seg * 16, bsl + seg * 8);
        }
    }
    cp_commit();

    // A cp.async ring
    const int cprow = t >> 2, cpseg = t & 3;
    const __nv_bfloat16* xh = g_Xh + (size_t)(m0 + cprow) * 256 + cpseg * 8;
    const __nv_bfloat16* xl = g_Xl + (size_t)(m0 + cprow) * 256 + cpseg * 8;
    const uint32_t adst = s2u(dsm) + cprow * 80 + cpseg * 16;
#define CP_A(S)                                                               \
    {                                                                         \
        uint32_t sl = ((uint32_t)(S) & 3u) * 10240u;                          \
        cp16(adst + sl,        xh + (S) * 32);                                \
        cp16(adst + sl + 5120, xl + (S) * 32);                                \
    }
    CP_A(0) cp_commit();
    CP_A(1) cp_commit();
    CP_A(2) cp_commit();

    float acc[4][4];
#pragma unroll
    for (int nt = 0; nt < 4; nt++)
#pragma unroll
        for (int q = 0; q < 4; q++) acc[nt][q] = 0.f;

    const uint32_t abase = s2u(dsm) + (wm * 16 + r0) * 80 + c0 * 4;
    const uint32_t bbase = s2u(dsm) + GB_OFF + (wc * 32 + r0) * GB_STRIDE + c0 * 4;

    for (int s = 0; s < 8; s++) {
        cp_wait<2>();
        __syncthreads();
        if (s < 5) CP_A(s + 3)
        cp_commit();
        const uint32_t ab = abase + ((uint32_t)s & 3u) * 10240u;
#pragma unroll
        for (int ck = 0; ck < 2; ck++) {
            uint2 Ah0 = lds64(ab + ck * 32);
            uint2 Ah1 = lds64(ab + ck * 32 + 8 * 80);
            uint2 Al0 = lds64(ab + 5120 + ck * 32);
            uint2 Al1 = lds64(ab + 5120 + ck * 32 + 8 * 80);
            const uint32_t bk = bbase + (s * 32 + ck * 16) * 2;
#pragma unroll
            for (int nt = 0; nt < 4; nt++) {
                uint2 Bh = lds64(bk + nt * 8 * GB_STRIDE);
                uint2 Bl = lds64(bk + nt * 8 * GB_STRIDE + GB_PLANE);
                mma16816(acc[nt], Ah0.x, Ah1.x, Ah0.y, Ah1.y, Bh.x, Bh.y);
                mma16816(acc[nt], Ah0.x, Ah1.x, Ah0.y, Ah1.y, Bl.x, Bl.y);
                mma16816(acc[nt], Al0.x, Al1.x, Al0.y, Al1.y, Bh.x, Bh.y);
            }
        }
    }
#undef CP_A
    __syncthreads();

    // ---- epilogue: stage Wh tile as sT[c][m] fp32 (aliases A ring) ----
    float* sT = reinterpret_cast<float*>(dsm);           // [64][68]
#pragma unroll
    for (int nt = 0; nt < 4; nt++) {
        const int c = wc * 32 + nt * 8 + c0;
        const int m = wm * 16 + r0;
        sT[(c + 0) * 68 + m]     = acc[nt][0];
        sT[(c + 1) * 68 + m]     = acc[nt][1];
        sT[(c + 0) * 68 + m + 8] = acc[nt][2];
        sT[(c + 1) * 68 + m + 8] = acc[nt][3];
    }
    __syncthreads();

    // (a) transposed bf16 hi/lo WhT write
    {
        const int c   = t >> 2;
        const int seg = t & 3;
        const int b   = bm >> 4;
        const int n0  = (bm & 15) * 64 + seg * 16;
        const int h   = 2 * bn + (c >> 5);
        const int d   = c & 31;
        float v[16];
        const float4* rp = reinterpret_cast<const float4*>(&sT[c * 68 + seg * 16]);
#pragma unroll
        for (int q = 0; q < 4; q++) {
            float4 f = rp[q];
            v[q * 4 + 0] = f.x; v[q * 4 + 1] = f.y;
            v[q * 4 + 2] = f.z; v[q * 4 + 3] = f.w;
        }
        uint32_t H[8], L[8];
        split16(v, H, L);
        const size_t off = (size_t)(b * 8 + h) * 32768 + (size_t)d * 1024 + n0;
        uint4* dh = reinterpret_cast<uint4*>(g_WhT_hi + off);
        uint4* dl = reinterpret_cast<uint4*>(g_WhT_lo + off);
        dh[0] = make_uint4(H[0], H[1], H[2], H[3]);
        dh[1] = make_uint4(H[4], H[5], H[6], H[7]);
        dl[0] = make_uint4(L[0], L[1], L[2], L[3]);
        dl[1] = make_uint4(L[4], L[5], L[6], L[7]);
    }

    // (b) e1/e2 + per-bh max atomics
    if (t < 128) {
        const int hh = t >> 6, r = t & 63;
        float e1 = 0.f, e2 = 0.f;
#pragma unroll
        for (int d = 0; d < 32; d++) {
            float v = sT[(hh * 32 + d) * 68 + r];
            e1 = fmaf(v, sa[hh * 64 + d], e1);
            e2 = fmaf(v, sa[hh * 64 + 32 + d], e2);
        }
        const int m  = m0 + r;
        const int b  = m >> 10, n = m & 1023;
        const int bh = b * 8 + bn * 2 + hh;
        g_e1[bh * 1024 + n] = e1;
        g_e2[bh * 1024 + n] = e2;

        float m1 = e1, m2 = e2;
#pragma unroll
        for (int off = 16; off; off >>= 1) {
            m1 = fmaxf(m1, __shfl_xor_sync(0xffffffffu, m1, off));
            m2 = fmaxf(m2, __shfl_xor_sync(0xffffffffu, m2, off));
        }
        if (lane == 0) {
            atomicMax(&g_M1u[bh], encf(m1));
            atomicMax(&g_M2u[bh], encf(m2));
        }
    }
}

// ---------------- Kernel E: per-j softmax factor pairs -----------------------
// Bp = exp(e2 - C + M1), Bm = exp(0.2*e2 - C + 0.2*M1); both <= 1.
__global__ __launch_bounds__(256) void expj_k() {
    const int idx = blockIdx.x * 256 + threadIdx.x;     // 65536
    const int bh  = idx >> 10;
    const float M1 = decf(g_M1u[bh]);
    const float M2 = decf(g_M2u[bh]);
    const float s  = M1 + M2;
    const float C  = fmaxf(s, 0.2f * s);
    const float e2 = g_e2[idx];
    float2 r;
    r.x = __expf(e2 - C + M1);
    r.y = __expf(fmaf(0.2f, e2, fmaf(0.2f, M1, -C)));
    reinterpret_cast<float2*>(g_E2f)[idx] = r;
}

// ---------------- Kernel D: HMMA fused softmax + attn@Wh ---------------------
// p_ij = mask * max(Ap_i*Bp_j, Am_i*Bm_j)  — exact leaky-softmax factorization,
// zero MUFU in the main loop.
__global__ __launch_bounds__(256, 2) void gat_mma_k(const float* __restrict__ bias,
                                                    float* __restrict__ out) {
    __shared__ __align__(16) __nv_bfloat16 sB[4][2][32][72];  // [slot][hi/lo][d][j]

    const int t    = threadIdx.x;
    const int w    = t >> 5;
    const int lane = t & 31;
    const int bh   = blockIdx.y;
    const int b    = bh >> 3, h = bh & 7;
    const int i0   = blockIdx.x * 128;

    const int r0 = lane >> 2;
    const int c0 = (lane & 3) * 2;

    const int   row0 = w * 16 + r0;
    const float M1   = decf(g_M1u[bh]);
    const float e1_0 = g_e1[bh * 1024 + i0 + row0];
    const float e1_1 = g_e1[bh * 1024 + i0 + row0 + 8];
    const float Ap0 = __expf(e1_0 - M1), Am0 = __expf(0.2f * (e1_0 - M1));
    const float Ap1 = __expf(e1_1 - M1), Am1 = __expf(0.2f * (e1_1 - M1));

    const unsigned* __restrict__ mrow0 = g_adjbits + (size_t)(b * 1024 + i0 + row0) * 32;
    const unsigned* __restrict__ mrow1 = mrow0 + 8 * 32;
    const float* __restrict__ e2f = g_E2f + (size_t)bh * 2048;

    const int cpd = t >> 3, cpj = (t & 7) * 8;
    const __nv_bfloat16* bsrc_hi = g_WhT_hi + (size_t)bh * 32768 + cpd * 1024 + cpj;
    const __nv_bfloat16* bsrc_lo = g_WhT_lo + (size_t)bh * 32768 + cpd * 1024 + cpj;
#define CP_B(C_)                                                              \
    {                                                                         \
        int sl = (C_) & 3;                                                    \
        cp16(s2u(&sB[sl][0][cpd][cpj]), bsrc_hi + (C_) * 64);                 \
        cp16(s2u(&sB[sl][1][cpd][cpj]), bsrc_lo + (C_) * 64);                 \
    }
    CP_B(0) cp_commit();
    CP_B(1) cp_commit();
    CP_B(2) cp_commit();

    float acc[4][4];
#pragma unroll
    for (int nt = 0; nt < 4; nt++)
#pragma unroll
        for (int q = 0; q < 4; q++) acc[nt][q] = 0.f;
    float den0 = 0.f, den1 = 0.f;

    for (int c = 0; c < 16; c++) {
        cp_wait<2>();
        __syncthreads();
        if (c < 13) CP_B(c + 3)
        cp_commit();
        const int sl = c & 3;

        const unsigned m0a = mrow0[2 * c], m0b = mrow0[2 * c + 1];
        const unsigned m1a = mrow1[2 * c], m1b = mrow1[2 * c + 1];

#pragma unroll
        for (int kt = 0; kt < 4; kt++) {
            const int jb = c * 64 + kt * 16;
            // (Bp,Bm) pairs for j = jb+c0, jb+c0+1 and jb+c0+8, jb+c0+9
            float4 F0 = *reinterpret_cast<const float4*>(e2f + 2 * (jb + c0));
            float4 F1 = *reinterpret_cast<const float4*>(e2f + 2 * (jb + c0 + 8));
            const int sh = ((kt & 1) * 16) + c0;
            const unsigned bits0 = ((kt >> 1) ? m0b : m0a) >> sh;
            const unsigned bits1 = ((kt >> 1) ? m1b : m1a) >> sh;

#define PP(DST, AP, AM, BP, BM, BITS, POS)                                    \
            float DST;                                                        \
            {                                                                 \
                float pe = fmaxf((AP) * (BP), (AM) * (BM));                   \
                DST = (((BITS) >> (POS)) & 1u) ? pe : 0.f;                    \
            }
            PP(p00, Ap0, Am0, F0.x, F0.y, bits0, 0)
            PP(p01, Ap0, Am0, F0.z, F0.w, bits0, 1)
            PP(p08, Ap0, Am0, F1.x, F1.y, bits0, 8)
            PP(p09, Ap0, Am0, F1.z, F1.w, bits0, 9)
            PP(p10, Ap1, Am1, F0.x, F0.y, bits1, 0)
            PP(p11, Ap1, Am1, F0.z, F0.w, bits1, 1)
            PP(p18, Ap1, Am1, F1.x, F1.y, bits1, 8)
            PP(p19, Ap1, Am1, F1.z, F1.w, bits1, 9)
#undef PP
            den0 += (p00 + p01) + (p08 + p09);
            den1 += (p10 + p11) + (p18 + p19);

            uint32_t ah0 = cvt2bf(p01, p00);
            uint32_t ah1 = cvt2bf(p11, p10);
            uint32_t ah2 = cvt2bf(p09, p08);
            uint32_t ah3 = cvt2bf(p19, p18);
            uint32_t al0 = cvt2bf(p01 - __uint_as_float(ah0 & 0xffff0000u),
                                  p00 - __uint_as_float(ah0 << 16));
            uint32_t al1 = cvt2bf(p11 - __uint_as_float(ah1 & 0xffff0000u),
                                  p10 - __uint_as_float(ah1 << 16));
            uint32_t al2 = cvt2bf(p09 - __uint_as_float(ah2 & 0xffff0000u),
                                  p08 - __uint_as_float(ah2 << 16));
            uint32_t al3 = cvt2bf(p19 - __uint_as_float(ah3 & 0xffff0000u),
                                  p18 - __uint_as_float(ah3 << 16));

#pragma unroll
            for (int nt = 0; nt < 4; nt++) {
                uint2 bhp = *reinterpret_cast<const uint2*>(
                    &sB[sl][0][nt * 8 + r0][kt * 16 + c0 * 2]);
                uint2 blp = *reinterpret_cast<const uint2*>(
                    &sB[sl][1][nt * 8 + r0][kt * 16 + c0 * 2]);
                mma16816(acc[nt], ah0, ah1, ah2, ah3, bhp.x, bhp.y);
                mma16816(acc[nt], ah0, ah1, ah2, ah3, blp.x, blp.y);
                mma16816(acc[nt], al0, al1, al2, al3, bhp.x, bhp.y);
            }
        }
    }
#undef CP_B

    den0 += __shfl_xor_sync(0xffffffffu, den0, 1);
    den0 += __shfl_xor_sync(0xffffffffu, den0, 2);
    den1 += __shfl_xor_sync(0xffffffffu, den1, 1);
    den1 += __shfl_xor_sync(0xffffffffu, den1, 2);
    const float rd0 = 1.0f / den0;
    const float rd1 = 1.0f / den1;

    float* o0 = out + ((size_t)(b * 1024 + i0 + row0)) * 256 + h * 32;
    float* o1 = o0 + 8 * 256;
#pragma unroll
    for (int nt = 0; nt < 4; nt++) {
        const int dcol = nt * 8 + c0;
        float2 bi = *reinterpret_cast<const float2*>(bias + h * 32 + dcol);
        float2 v0, v1;
        v0.x = fmaxf(acc[nt][0] * rd0 + bi.x, 0.f);
        v0.y = fmaxf(acc[nt][1] * rd0 + bi.y, 0.f);
        v1.x = fmaxf(acc[nt][2] * rd1 + bi.x, 0.f);
        v1.y = fmaxf(acc[nt][3] * rd1 + bi.y, 0.f);
        *reinterpret_cast<float2*>(o0 + dcol) = v0;
        *reinterpret_cast<float2*>(o1 + dcol) = v1;
    }
}

// ---------------- launcher ---------------------------------------------------
extern "C" void kernel_launch(void* const* d_in, const int* in_sizes, int n_in,
                              void* d_out, int out_size) {
    const float* nf   = (const float*)d_in[0];   // (8,1024,256)
    const int*   adj  = (const int*)d_in[1];     // (8,1024,1024)
    const float* W    = (const float*)d_in[2];   // (8,256,32)
    const float* a    = (const float*)d_in[3];   // (8,64)
    const float* bias = (const float*)d_in[4];   // (256,)
    float*       out  = (float*)d_out;           // (8,1024,256)

    cudaFuncSetAttribute(gemm_mma_k, cudaFuncAttributeMaxDynamicSharedMemorySize,
                         GSM_TOTAL);

    split_x_k<<<512, 256>>>(nf);
    split_w_k<<<16, 256>>>(W);
    bitpack_k<<<1024, 256>>>(adj);
    gemm_mma_k<<<dim3(128, 4), 256, GSM_TOTAL>>>(a);
    expj_k<<<256, 256>>>();
    gat_mma_k<<<dim3(8, 64), 256>>>(bias, out);
}

// round 13
// speedup vs baseline: 2.4957x; 1.0341x over previous
#include <cuda_runtime.h>
#include <cuda_bf16.h>
#include <cuda_fp16.h>
#include <cstdint>
#include <cstddef>

typedef unsigned long long ull;

// ---------------- scratch (static device globals; no runtime alloc) ----------
__device__ __align__(16) float g_e1[65536];            // [(b*8+h)*1024 + n]
__device__ __align__(16) float g_e2[65536];
__device__ __align__(16) float g_E2f[65536 * 2];       // per-j factor pair (Bp,Bm)
__device__ __align__(16) unsigned g_M1u[64];           // per-bh max e1 (encoded)
__device__ __align__(16) unsigned g_M2u[64];           // per-bh max e2 (encoded)
__device__ __align__(16) unsigned g_adjbits[8 * 1024 * 32];          // 1 MB
// k-pair-interleaved bf16 splits for the Wh GEMM inputs
__device__ __align__(16) __nv_bfloat16 g_Xh[8192 * 256];             // [m][k]
__device__ __align__(16) __nv_bfloat16 g_Xl[8192 * 256];
__device__ __align__(16) __nv_bfloat16 g_WT_hi[256 * 256];           // [h*32+d][k]
__device__ __align__(16) __nv_bfloat16 g_WT_lo[256 * 256];
// WhT for attention GEMM: fp16 hi/lo, [bh][d][n], j-pair interleaved
__device__ __align__(16) __half g_WhT_hi[64 * 32 * 1024];
__device__ __align__(16) __half g_WhT_lo[64 * 32 * 1024];

// ---------------- small PTX helpers ------------------------------------------
__device__ __forceinline__ uint32_t s2u(const void* p) {
    return (uint32_t)__cvta_generic_to_shared(p);
}
__device__ __forceinline__ void cp16(uint32_t dst, const void* src) {
    asm volatile("cp.async.cg.shared.global [%0], [%1], 16;" :: "r"(dst), "l"(src));
}
__device__ __forceinline__ void cp_commit() { asm volatile("cp.async.commit_group;"); }
template <int N> __device__ __forceinline__ void cp_wait() {
    asm volatile("cp.async.wait_group %0;" :: "n"(N));
}
// pack: low half = bf16(l), high half = bf16(h)
__device__ __forceinline__ uint32_t cvt2bf(float h, float l) {
    uint32_t r; asm("cvt.rn.bf16x2.f32 %0, %1, %2;" : "=r"(r) : "f"(h), "f"(l)); return r;
}
// pack two fp32 -> f16x2, low half = a
__device__ __forceinline__ uint32_t cvt2h(float a, float b) {
    uint32_t r; asm("cvt.rn.f16x2.f32 %0, %1, %2;" : "=r"(r) : "f"(b), "f"(a)); return r;
}
__device__ __forceinline__ uint2 lds64(uint32_t a) {
    uint2 v;
    asm volatile("ld.shared.v2.b32 {%0,%1}, [%2];" : "=r"(v.x), "=r"(v.y) : "r"(a));
    return v;
}
// D(16x8,f32) += A(16x16,bf16,row) * B(16x8,bf16,col)
__device__ __forceinline__ void mma16816(float* d,
                                         uint32_t a0, uint32_t a1, uint32_t a2, uint32_t a3,
                                         uint32_t b0, uint32_t b1) {
    asm volatile(
        "mma.sync.aligned.m16n8k16.row.col.f32.bf16.bf16.f32 "
        "{%0,%1,%2,%3}, {%4,%5,%6,%7}, {%8,%9}, {%0,%1,%2,%3};"
        : "+f"(d[0]), "+f"(d[1]), "+f"(d[2]), "+f"(d[3])
        : "r"(a0), "r"(a1), "r"(a2), "r"(a3), "r"(b0), "r"(b1));
}
// fp16 variant
__device__ __forceinline__ void mma16816h(float* d,
                                          uint32_t a0, uint32_t a1, uint32_t a2, uint32_t a3,
                                          uint32_t b0, uint32_t b1) {
    asm volatile(
        "mma.sync.aligned.m16n8k16.row.col.f32.f16.f16.f32 "
        "{%0,%1,%2,%3}, {%4,%5,%6,%7}, {%8,%9}, {%0,%1,%2,%3};"
        : "+f"(d[0]), "+f"(d[1]), "+f"(d[2]), "+f"(d[3])
        : "r"(a0), "r"(a1), "r"(a2), "r"(a3), "r"(b0), "r"(b1));
}
// monotone float<->uint encoding for atomicMax over signed floats
__device__ __forceinline__ unsigned encf(float f) {
    unsigned u = __float_as_uint(f);
    return (u & 0x80000000u) ? ~u : (u | 0x80000000u);
}
__device__ __forceinline__ float decf(unsigned k) {
    unsigned u = (k & 0x80000000u) ? (k ^ 0x80000000u) : ~k;
    return __uint_as_float(u);
}
// split 16 fp32 -> 8 hi + 8 lo bf16x2 words, k-pair interleaved
__device__ __forceinline__ void split16(const float* v, uint32_t* H, uint32_t* L) {
    const int perm[8] = {0, 8, 2, 10, 4, 12, 6, 14};
#pragma unroll
    for (int m = 0; m < 8; m++) {
        float f0 = v[perm[m]], f1 = v[perm[m] + 1];
        uint32_t hw = cvt2bf(f1, f0);
        float r0 = f0 - __uint_as_float(hw << 16);
        float r1 = f1 - __uint_as_float(hw & 0xffff0000u);
        H[m] = hw;
        L[m] = cvt2bf(r1, r0);
    }
}
// split 16 fp32 -> 8 hi + 8 lo f16x2 words, k-pair interleaved
__device__ __forceinline__ void split16h(const float* v, uint32_t* H, uint32_t* L) {
    const int perm[8] = {0, 8, 2, 10, 4, 12, 6, 14};
#pragma unroll
    for (int m = 0; m < 8; m++) {
        float f0 = v[perm[m]], f1 = v[perm[m] + 1];
        __half2 hh = __floats2half2_rn(f0, f1);        // x (low) = f0
        float2  bk = __half22float2(hh);
        __half2 ll = __floats2half2_rn(f0 - bk.x, f1 - bk.y);
        H[m] = *reinterpret_cast<const uint32_t*>(&hh);
        L[m] = *reinterpret_cast<const uint32_t*>(&ll);
    }
}

// ---------------- Kernel P1: split X fp32 -> bf16 hi/lo (interleaved) --------
__global__ __launch_bounds__(256) void split_x_k(const float* __restrict__ X) {
    const int g = blockIdx.x * 256 + threadIdx.x;
    float v[16];
    const float4* s4 = reinterpret_cast<const float4*>(X + (size_t)g * 16);
#pragma unroll
    for (int q = 0; q < 4; q++) {
        float4 f = s4[q];
        v[q * 4 + 0] = f.x; v[q * 4 + 1] = f.y;
        v[q * 4 + 2] = f.z; v[q * 4 + 3] = f.w;
    }
    uint32_t H[8], L[8];
    split16(v, H, L);
    uint4* dh = reinterpret_cast<uint4*>(g_Xh + (size_t)g * 16);
    uint4* dl = reinterpret_cast<uint4*>(g_Xl + (size_t)g * 16);
    dh[0] = make_uint4(H[0], H[1], H[2], H[3]);
    dh[1] = make_uint4(H[4], H[5], H[6], H[7]);
    dl[0] = make_uint4(L[0], L[1], L[2], L[3]);
    dl[1] = make_uint4(L[4], L[5], L[6], L[7]);
}

// ---------------- Kernel P2: split/transpose W + init max keys ---------------
__global__ __launch_bounds__(256) void split_w_k(const float* __restrict__ W) {
    const int t = threadIdx.x;
    if (blockIdx.x == 0 && t < 64) { g_M1u[t] = 0u; g_M2u[t] = 0u; }
    const int task = blockIdx.x * 256 + t;
    const int h   = task >> 9;
    const int d   = (task >> 4) & 31;
    const int grp = task & 15;
    const float* wp = W + (size_t)h * 8192 + (size_t)grp * 16 * 32 + d;
    float v[16];
#pragma unroll
    for (int k = 0; k < 16; k++) v[k] = wp[k * 32];
    uint32_t H[8], L[8];
    split16(v, H, L);
    const size_t off = (size_t)(h * 32 + d) * 256 + grp * 16;
    uint4* dh = reinterpret_cast<uint4*>(g_WT_hi + off);
    uint4* dl = reinterpret_cast<uint4*>(g_WT_lo + off);
    dh[0] = make_uint4(H[0], H[1], H[2], H[3]);
    dh[1] = make_uint4(H[4], H[5], H[6], H[7]);
    dl[0] = make_uint4(L[0], L[1], L[2], L[3]);
    dl[1] = make_uint4(L[4], L[5], L[6], L[7]);
}

// ---------------- Kernel A2: bitpack adjacency -------------------------------
__global__ __launch_bounds__(256) void bitpack_k(const int* __restrict__ adj) {
    const int w = blockIdx.x * 256 + threadIdx.x;
    const int4* p = reinterpret_cast<const int4*>(adj) + (size_t)w * 8;
    unsigned bits = 0;
#pragma unroll
    for (int k = 0; k < 8; k++) {
        int4 v = p[k];
        bits |= (unsigned)(v.x != 0) << (k * 4 + 0);
        bits |= (unsigned)(v.y != 0) << (k * 4 + 1);
        bits |= (unsigned)(v.z != 0) << (k * 4 + 2);
        bits |= (unsigned)(v.w != 0) << (k * 4 + 3);
    }
    g_adjbits[w] = bits;
}

// ---------------- Kernel G: HMMA Wh GEMM + fused WhT/e1/e2/max epilogue ------
#define GB_OFF    40960
#define GB_PLANE  34816
#define GB_STRIDE 544
#define GSA_OFF   (GB_OFF + 2 * GB_PLANE)      // 110592
#define GSM_TOTAL (GSA_OFF + 512)              // 111104

__global__ __launch_bounds__(256) void gemm_mma_k(const float* __restrict__ av) {
    extern __shared__ __align__(16) char dsm[];
    float* sa = reinterpret_cast<float*>(dsm + GSA_OFF);

    const int t    = threadIdx.x;
    const int lane = t & 31;
    const int w    = t >> 5;
    const int bm   = blockIdx.x;
    const int bn   = blockIdx.y;
    const int m0   = bm * 64;
    const int wm   = w >> 1;
    const int wc   = w & 1;
    const int r0   = lane >> 2;
    const int c0   = (lane & 3) * 2;

    if (t < 32)
        reinterpret_cast<float4*>(sa)[t] =
            reinterpret_cast<const float4*>(av + bn * 128)[t];

    // one-time B staging
    {
        const int brow = t >> 2, bseg = t & 3;
        const uint32_t bdst = s2u(dsm) + GB_OFF + brow * GB_STRIDE;
        const __nv_bfloat16* bsh = g_WT_hi + (size_t)(bn * 64 + brow) * 256;
        const __nv_bfloat16* bsl = g_WT_lo + (size_t)(bn * 64 + brow) * 256;
#pragma unroll
        for (int q = 0; q < 8; q++) {
            const int seg = bseg + q * 4;
            cp16(bdst + seg * 16,            bsh + seg * 8);
            cp16(bdst + GB_PLANE + seg * 16, bsl + seg * 8);
        }
    }
    cp_commit();

    const int cprow = t >> 2, cpseg = t & 3;
    const __nv_bfloat16* xh = g_Xh + (size_t)(m0 + cprow) * 256 + cpseg * 8;
    const __nv_bfloat16* xl = g_Xl + (size_t)(m0 + cprow) * 256 + cpseg * 8;
    const uint32_t adst = s2u(dsm) + cprow * 80 + cpseg * 16;
#define CP_A(S)                                                               \
    {                                                                         \
        uint32_t sl = ((uint32_t)(S) & 3u) * 10240u;                          \
        cp16(adst + sl,        xh + (S) * 32);                                \
        cp16(adst + sl + 5120, xl + (S) * 32);                                \
    }
    CP_A(0) cp_commit();
    CP_A(1) cp_commit();
    CP_A(2) cp_commit();

    float acc[4][4];
#pragma unroll
    for (int nt = 0; nt < 4; nt++)
#pragma unroll
        for (int q = 0; q < 4; q++) acc[nt][q] = 0.f;

    const uint32_t abase = s2u(dsm) + (wm * 16 + r0) * 80 + c0 * 4;
    const uint32_t bbase = s2u(dsm) + GB_OFF + (wc * 32 + r0) * GB_STRIDE + c0 * 4;

    for (int s = 0; s < 8; s++) {
        cp_wait<2>();
        __syncthreads();
        if (s < 5) CP_A(s + 3)
        cp_commit();
        const uint32_t ab = abase + ((uint32_t)s & 3u) * 10240u;
#pragma unroll
        for (int ck = 0; ck < 2; ck++) {
            uint2 Ah0 = lds64(ab + ck * 32);
            uint2 Ah1 = lds64(ab + ck * 32 + 8 * 80);
            uint2 Al0 = lds64(ab + 5120 + ck * 32);
            uint2 Al1 = lds64(ab + 5120 + ck * 32 + 8 * 80);
            const uint32_t bk = bbase + (s * 32 + ck * 16) * 2;
#pragma unroll
            for (int nt = 0; nt < 4; nt++) {
                uint2 Bh = lds64(bk + nt * 8 * GB_STRIDE);
                uint2 Bl = lds64(bk + nt * 8 * GB_STRIDE + GB_PLANE);
                mma16816(acc[nt], Ah0.x, Ah1.x, Ah0.y, Ah1.y, Bh.x, Bh.y);
                mma16816(acc[nt], Ah0.x, Ah1.x, Ah0.y, Ah1.y, Bl.x, Bl.y);
                mma16816(acc[nt], Al0.x, Al1.x, Al0.y, Al1.y, Bh.x, Bh.y);
            }
        }
    }
#undef CP_A
    __syncthreads();

    // epilogue: stage Wh tile as sT[c][m] fp32 (aliases A ring)
    float* sT = reinterpret_cast<float*>(dsm);           // [64][68]
#pragma unroll
    for (int nt = 0; nt < 4; nt++) {
        const int c = wc * 32 + nt * 8 + c0;
        const int m = wm * 16 + r0;
        sT[(c + 0) * 68 + m]     = acc[nt][0];
        sT[(c + 1) * 68 + m]     = acc[nt][1];
        sT[(c + 0) * 68 + m + 8] = acc[nt][2];
        sT[(c + 1) * 68 + m + 8] = acc[nt][3];
    }
    __syncthreads();

    // (a) transposed fp16 hi/lo WhT write (layout gat_mma reads)
    {
        const int c   = t >> 2;
        const int seg = t & 3;
        const int b   = bm >> 4;
        const int n0  = (bm & 15) * 64 + seg * 16;
        const int h   = 2 * bn + (c >> 5);
        const int d   = c & 31;
        float v[16];
        const float4* rp = reinterpret_cast<const float4*>(&sT[c * 68 + seg * 16]);
#pragma unroll
        for (int q = 0; q < 4; q++) {
            float4 f = rp[q];
            v[q * 4 + 0] = f.x; v[q * 4 + 1] = f.y;
            v[q * 4 + 2] = f.z; v[q * 4 + 3] = f.w;
        }
        uint32_t H[8], L[8];
        split16h(v, H, L);
        const size_t off = (size_t)(b * 8 + h) * 32768 + (size_t)d * 1024 + n0;
        uint4* dh = reinterpret_cast<uint4*>(g_WhT_hi + off);
        uint4* dl = reinterpret_cast<uint4*>(g_WhT_lo + off);
        dh[0] = make_uint4(H[0], H[1], H[2], H[3]);
        dh[1] = make_uint4(H[4], H[5], H[6], H[7]);
        dl[0] = make_uint4(L[0], L[1], L[2], L[3]);
        dl[1] = make_uint4(L[4], L[5], L[6], L[7]);
    }

    // (b) e1/e2 + per-bh max atomics
    if (t < 128) {
        const int hh = t >> 6, r = t & 63;
        float e1 = 0.f, e2 = 0.f;
#pragma unroll
        for (int d = 0; d < 32; d++) {
            float v = sT[(hh * 32 + d) * 68 + r];
            e1 = fmaf(v, sa[hh * 64 + d], e1);
            e2 = fmaf(v, sa[hh * 64 + 32 + d], e2);
        }
        const int m  = m0 + r;
        const int b  = m >> 10, n = m & 1023;
        const int bh = b * 8 + bn * 2 + hh;
        g_e1[bh * 1024 + n] = e1;
        g_e2[bh * 1024 + n] = e2;

        float m1 = e1, m2 = e2;
#pragma unroll
        for (int off = 16; off; off >>= 1) {
            m1 = fmaxf(m1, __shfl_xor_sync(0xffffffffu, m1, off));
            m2 = fmaxf(m2, __shfl_xor_sync(0xffffffffu, m2, off));
        }
        if (lane == 0) {
            atomicMax(&g_M1u[bh], encf(m1));
            atomicMax(&g_M2u[bh], encf(m2));
        }
    }
}

// ---------------- Kernel E: per-j softmax factor pairs -----------------------
__global__ __launch_bounds__(256) void expj_k() {
    const int idx = blockIdx.x * 256 + threadIdx.x;     // 65536
    const int bh  = idx >> 10;
    const float M1 = decf(g_M1u[bh]);
    const float M2 = decf(g_M2u[bh]);
    const float s  = M1 + M2;
    const float C  = fmaxf(s, 0.2f * s);
    const float e2 = g_e2[idx];
    float2 r;
    r.x = __expf(e2 - C + M1);
    r.y = __expf(fmaf(0.2f, e2, fmaf(0.2f, M1, -C)));
    reinterpret_cast<float2*>(g_E2f)[idx] = r;
}

// ---------------- Kernel D: HMMA fused softmax + attn@Wh (fp16, rescaled) ----
// p'_ij = mask * max(Ap'_i*Bp_j, Am'_i*Bm_j), row-rescaled so max_j p' = 1.
// P single fp16 fragment; Wh fp16 hi/lo -> 2 MMAs per (nt,kt).
__global__ __launch_bounds__(256, 3) void gat_mma_k(const float* __restrict__ bias,
                                                    float* __restrict__ out) {
    __shared__ __align__(16) __half sB[4][2][32][72];   // [slot][hi/lo][d][j]

    const int t    = threadIdx.x;
    const int w    = t >> 5;
    const int lane = t & 31;
    const int bh   = blockIdx.y;
    const int b    = bh >> 3, h = bh & 7;
    const int i0   = blockIdx.x * 128;

    const int r0 = lane >> 2;
    const int c0 = (lane & 3) * 2;

    const int   row0 = w * 16 + r0;
    const float M1   = decf(g_M1u[bh]);
    const float M2   = decf(g_M2u[bh]);
    const float s    = M1 + M2;
    const float BPM  = (s >= 0.f) ? 1.f : __expf(0.8f * s);   // max_j Bp
    const float BMM  = (s >= 0.f) ? __expf(-0.8f * s) : 1.f;  // max_j Bm
    const float e1_0 = g_e1[bh * 1024 + i0 + row0];
    const float e1_1 = g_e1[bh * 1024 + i0 + row0 + 8];
    float Ap0 = __expf(e1_0 - M1), Am0 = __expf(0.2f * (e1_0 - M1));
    float Ap1 = __expf(e1_1 - M1), Am1 = __expf(0.2f * (e1_1 - M1));
    {   // per-row rescale: row max of p' becomes exactly 1 (fp16-safe)
        float rs0 = 1.f / fmaxf(Ap0 * BPM, Am0 * BMM);
        float rs1 = 1.f / fmaxf(Ap1 * BPM, Am1 * BMM);
        Ap0 *= rs0; Am0 *= rs0;
        Ap1 *= rs1; Am1 *= rs1;
    }

    const unsigned* __restrict__ mrow0 = g_adjbits + (size_t)(b * 1024 + i0 + row0) * 32;
    const unsigned* __restrict__ mrow1 = mrow0 + 8 * 32;
    const float* __restrict__ e2f = g_E2f + (size_t)bh * 2048;

    const int cpd = t >> 3, cpj = (t & 7) * 8;
    const __half* bsrc_hi = g_WhT_hi + (size_t)bh * 32768 + cpd * 1024 + cpj;
    const __half* bsrc_lo = g_WhT_lo + (size_t)bh * 32768 + cpd * 1024 + cpj;
#define CP_B(C_)                                                              \
    {                                                                         \
        int sl = (C_) & 3;                                                    \
        cp16(s2u(&sB[sl][0][cpd][cpj]), bsrc_hi + (C_) * 64);                 \
        cp16(s2u(&sB[sl][1][cpd][cpj]), bsrc_lo + (C_) * 64);                 \
    }
    CP_B(0) cp_commit();
    CP_B(1) cp_commit();
    CP_B(2) cp_commit();

    float acc[4][4];
#pragma unroll
    for (int nt = 0; nt < 4; nt++)
#pragma unroll
        for (int q = 0; q < 4; q++) acc[nt][q] = 0.f;
    float den0 = 0.f, den1 = 0.f;

    for (int c = 0; c < 16; c++) {
        cp_wait<2>();
        __syncthreads();
        if (c < 13) CP_B(c + 3)
        cp_commit();
        const int sl = c & 3;

        const unsigned m0a = mrow0[2 * c], m0b = mrow0[2 * c + 1];
        const unsigned m1a = mrow1[2 * c], m1b = mrow1[2 * c + 1];

#pragma unroll
        for (int kt = 0; kt < 4; kt++) {
            const int jb = c * 64 + kt * 16;
            float4 F0 = *reinterpret_cast<const float4*>(e2f + 2 * (jb + c0));
            float4 F1 = *reinterpret_cast<const float4*>(e2f + 2 * (jb + c0 + 8));
            const int sh = ((kt & 1) * 16) + c0;
            const unsigned bits0 = ((kt >> 1) ? m0b : m0a) >> sh;
            const unsigned bits1 = ((kt >> 1) ? m1b : m1a) >> sh;

#define PP(DST, AP, AM, BP, BM, BITS, POS)                                    \
            float DST;                                                        \
            {                                                                 \
                float pe = fmaxf((AP) * (BP), (AM) * (BM));                   \
                DST = (((BITS) >> (POS)) & 1u) ? pe : 0.f;                    \
            }
            PP(p00, Ap0, Am0, F0.x, F0.y, bits0, 0)
            PP(p01, Ap0, Am0, F0.z, F0.w, bits0, 1)
            PP(p08, Ap0, Am0, F1.x, F1.y, bits0, 8)
            PP(p09, Ap0, Am0, F1.z, F1.w, bits0, 9)
            PP(p10, Ap1, Am1, F0.x, F0.y, bits1, 0)
            PP(p11, Ap1, Am1, F0.z, F0.w, bits1, 1)
            PP(p18, Ap1, Am1, F1.x, F1.y, bits1, 8)
            PP(p19, Ap1, Am1, F1.z, F1.w, bits1, 9)
#undef PP
            den0 += (p00 + p01) + (p08 + p09);
            den1 += (p10 + p11) + (p18 + p19);

            // single fp16 A fragment (11-bit mantissa covers p in [0,1])
            uint32_t a0 = cvt2h(p00, p01);
            uint32_t a1 = cvt2h(p10, p11);
            uint32_t a2 = cvt2h(p08, p09);
            uint32_t a3 = cvt2h(p18, p19);

#pragma unroll
            for (int nt = 0; nt < 4; nt++) {
                uint2 bhp = *reinterpret_cast<const uint2*>(
                    &sB[sl][0][nt * 8 + r0][kt * 16 + c0 * 2]);
                uint2 blp = *reinterpret_cast<const uint2*>(
                    &sB[sl][1][nt * 8 + r0][kt * 16 + c0 * 2]);
                mma16816h(acc[nt], a0, a1, a2, a3, bhp.x, bhp.y);
                mma16816h(acc[nt], a0, a1, a2, a3, blp.x, blp.y);
            }
        }
    }
#undef CP_B

    den0 += __shfl_xor_sync(0xffffffffu, den0, 1);
    den0 += __shfl_xor_sync(0xffffffffu, den0, 2);
    den1 += __shfl_xor_sync(0xffffffffu, den1, 1);
    den1 += __shfl_xor_sync(0xffffffffu, den1, 2);
    const float rd0 = 1.0f / den0;
    const float rd1 = 1.0f / den1;

    float* o0 = out + ((size_t)(b * 1024 + i0 + row0)) * 256 + h * 32;
    float* o1 = o0 + 8 * 256;
#pragma unroll
    for (int nt = 0; nt < 4; nt++) {
        const int dcol = nt * 8 + c0;
        float2 bi = *reinterpret_cast<const float2*>(bias + h * 32 + dcol);
        float2 v0, v1;
        v0.x = fmaxf(acc[nt][0] * rd0 + bi.x, 0.f);
        v0.y = fmaxf(acc[nt][1] * rd0 + bi.y, 0.f);
        v1.x = fmaxf(acc[nt][2] * rd1 + bi.x, 0.f);
        v1.y = fmaxf(acc[nt][3] * rd1 + bi.y, 0.f);
        *reinterpret_cast<float2*>(o0 + dcol) = v0;
        *reinterpret_cast<float2*>(o1 + dcol) = v1;
    }
}

// ---------------- launcher ---------------------------------------------------
extern "C" void kernel_launch(void* const* d_in, const int* in_sizes, int n_in,
                              void* d_out, int out_size) {
    const float* nf   = (const float*)d_in[0];   // (8,1024,256)
    const int*   adj  = (const int*)d_in[1];     // (8,1024,1024)
    const float* W    = (const float*)d_in[2];   // (8,256,32)
    const float* a    = (const float*)d_in[3];   // (8,64)
    const float* bias = (const float*)d_in[4];   // (256,)
    float*       out  = (float*)d_out;           // (8,1024,256)

    cudaFuncSetAttribute(gemm_mma_k, cudaFuncAttributeMaxDynamicSharedMemorySize,
                         GSM_TOTAL);

    split_x_k<<<512, 256>>>(nf);
    split_w_k<<<16, 256>>>(W);
    bitpack_k<<<1024, 256>>>(adj);
    gemm_mma_k<<<dim3(128, 4), 256, GSM_TOTAL>>>(a);
    expj_k<<<256, 256>>>();
    gat_mma_k<<<dim3(8, 64), 256>>>(bias, out);
}

// round 14
// speedup vs baseline: 2.9371x; 1.1769x over previous
#include <cuda_runtime.h>
#include <cuda_bf16.h>
#include <cuda_fp16.h>
#include <cstdint>
#include <cstddef>

typedef unsigned long long ull;

// ---------------- scratch (static device globals; no runtime alloc) ----------
__device__ __align__(16) float g_e1[65536];            // [(b*8+h)*1024 + n]
__device__ __align__(16) float g_e2[65536];
__device__ __align__(16) float g_E2f[65536 * 2];       // per-j factor pair (Bp,Bm)
__device__ __align__(16) unsigned g_M1u[64];           // per-bh max e1 (encoded)
__device__ __align__(16) unsigned g_M2u[64];           // per-bh max e2 (encoded)
__device__ __align__(16) unsigned g_adjbits[8 * 1024 * 32];          // 1 MB
// k-pair-interleaved bf16 splits for the Wh GEMM inputs
__device__ __align__(16) __nv_bfloat16 g_Xh[8192 * 256];             // [m][k]
__device__ __align__(16) __nv_bfloat16 g_Xl[8192 * 256];
__device__ __align__(16) __nv_bfloat16 g_WT_hi[256 * 256];           // [h*32+d][k]
__device__ __align__(16) __nv_bfloat16 g_WT_lo[256 * 256];
// WhT for attention GEMM: fp16 hi/lo, [bh][d][n], j-pair interleaved
__device__ __align__(16) __half g_WhT_hi[64 * 32 * 1024];
__device__ __align__(16) __half g_WhT_lo[64 * 32 * 1024];

// ---------------- small PTX helpers ------------------------------------------
__device__ __forceinline__ uint32_t s2u(const void* p) {
    return (uint32_t)__cvta_generic_to_shared(p);
}
__device__ __forceinline__ void cp16(uint32_t dst, const void* src) {
    asm volatile("cp.async.cg.shared.global [%0], [%1], 16;" :: "r"(dst), "l"(src));
}
__device__ __forceinline__ void cp_commit() { asm volatile("cp.async.commit_group;"); }
template <int N> __device__ __forceinline__ void cp_wait() {
    asm volatile("cp.async.wait_group %0;" :: "n"(N));
}
// pack: low half = bf16(l), high half = bf16(h)
__device__ __forceinline__ uint32_t cvt2bf(float h, float l) {
    uint32_t r; asm("cvt.rn.bf16x2.f32 %0, %1, %2;" : "=r"(r) : "f"(h), "f"(l)); return r;
}
// pack two fp32 -> f16x2, low half = a
__device__ __forceinline__ uint32_t cvt2h(float a, float b) {
    uint32_t r; asm("cvt.rn.f16x2.f32 %0, %1, %2;" : "=r"(r) : "f"(b), "f"(a)); return r;
}
__device__ __forceinline__ uint2 lds64(uint32_t a) {
    uint2 v;
    asm volatile("ld.shared.v2.b32 {%0,%1}, [%2];" : "=r"(v.x), "=r"(v.y) : "r"(a));
    return v;
}
// D(16x8,f32) += A(16x16,bf16,row) * B(16x8,bf16,col)
__device__ __forceinline__ void mma16816(float* d,
                                         uint32_t a0, uint32_t a1, uint32_t a2, uint32_t a3,
                                         uint32_t b0, uint32_t b1) {
    asm volatile(
        "mma.sync.aligned.m16n8k16.row.col.f32.bf16.bf16.f32 "
        "{%0,%1,%2,%3}, {%4,%5,%6,%7}, {%8,%9}, {%0,%1,%2,%3};"
        : "+f"(d[0]), "+f"(d[1]), "+f"(d[2]), "+f"(d[3])
        : "r"(a0), "r"(a1), "r"(a2), "r"(a3), "r"(b0), "r"(b1));
}
// fp16 variant
__device__ __forceinline__ void mma16816h(float* d,
                                          uint32_t a0, uint32_t a1, uint32_t a2, uint32_t a3,
                                          uint32_t b0, uint32_t b1) {
    asm volatile(
        "mma.sync.aligned.m16n8k16.row.col.f32.f16.f16.f32 "
        "{%0,%1,%2,%3}, {%4,%5,%6,%7}, {%8,%9}, {%0,%1,%2,%3};"
        : "+f"(d[0]), "+f"(d[1]), "+f"(d[2]), "+f"(d[3])
        : "r"(a0), "r"(a1), "r"(a2), "r"(a3), "r"(b0), "r"(b1));
}
// monotone float<->uint encoding for atomicMax over signed floats
__device__ __forceinline__ unsigned encf(float f) {
    unsigned u = __float_as_uint(f);
    return (u & 0x80000000u) ? ~u : (u | 0x80000000u);
}
__device__ __forceinline__ float decf(unsigned k) {
    unsigned u = (k & 0x80000000u) ? (k ^ 0x80000000u) : ~k;
    return __uint_as_float(u);
}
// split 16 fp32 -> 8 hi + 8 lo bf16x2 words, k-pair interleaved
__device__ __forceinline__ void split16(const float* v, uint32_t* H, uint32_t* L) {
    const int perm[8] = {0, 8, 2, 10, 4, 12, 6, 14};
#pragma unroll
    for (int m = 0; m < 8; m++) {
        float f0 = v[perm[m]], f1 = v[perm[m] + 1];
        uint32_t hw = cvt2bf(f1, f0);
        float r0 = f0 - __uint_as_float(hw << 16);
        float r1 = f1 - __uint_as_float(hw & 0xffff0000u);
        H[m] = hw;
        L[m] = cvt2bf(r1, r0);
    }
}
// split 16 fp32 -> 8 hi + 8 lo f16x2 words, k-pair interleaved
__device__ __forceinline__ void split16h(const float* v, uint32_t* H, uint32_t* L) {
    const int perm[8] = {0, 8, 2, 10, 4, 12, 6, 14};
#pragma unroll
    for (int m = 0; m < 8; m++) {
        float f0 = v[perm[m]], f1 = v[perm[m] + 1];
        __half2 hh = __floats2half2_rn(f0, f1);        // x (low) = f0
        float2  bk = __half22float2(hh);
        __half2 ll = __floats2half2_rn(f0 - bk.x, f1 - bk.y);
        H[m] = *reinterpret_cast<const uint32_t*>(&hh);
        L[m] = *reinterpret_cast<const uint32_t*>(&ll);
    }
}

// ---------------- Kernel P1: split X fp32 -> bf16 hi/lo (interleaved) --------
__global__ __launch_bounds__(256) void split_x_k(const float* __restrict__ X) {
    const int g = blockIdx.x * 256 + threadIdx.x;
    float v[16];
    const float4* s4 = reinterpret_cast<const float4*>(X + (size_t)g * 16);
#pragma unroll
    for (int q = 0; q < 4; q++) {
        float4 f = s4[q];
        v[q * 4 + 0] = f.x; v[q * 4 + 1] = f.y;
        v[q * 4 + 2] = f.z; v[q * 4 + 3] = f.w;
    }
    uint32_t H[8], L[8];
    split16(v, H, L);
    uint4* dh = reinterpret_cast<uint4*>(g_Xh + (size_t)g * 16);
    uint4* dl = reinterpret_cast<uint4*>(g_Xl + (size_t)g * 16);
    dh[0] = make_uint4(H[0], H[1], H[2], H[3]);
    dh[1] = make_uint4(H[4], H[5], H[6], H[7]);
    dl[0] = make_uint4(L[0], L[1], L[2], L[3]);
    dl[1] = make_uint4(L[4], L[5], L[6], L[7]);
}

// ---------------- Kernel P2: split/transpose W + init max keys ---------------
__global__ __launch_bounds__(256) void split_w_k(const float* __restrict__ W) {
    const int t = threadIdx.x;
    if (blockIdx.x == 0 && t < 64) { g_M1u[t] = 0u; g_M2u[t] = 0u; }
    const int task = blockIdx.x * 256 + t;
    const int h   = task >> 9;
    const int d   = (task >> 4) & 31;
    const int grp = task & 15;
    const float* wp = W + (size_t)h * 8192 + (size_t)grp * 16 * 32 + d;
    float v[16];
#pragma unroll
    for (int k = 0; k < 16; k++) v[k] = wp[k * 32];
    uint32_t H[8], L[8];
    split16(v, H, L);
    const size_t off = (size_t)(h * 32 + d) * 256 + grp * 16;
    uint4* dh = reinterpret_cast<uint4*>(g_WT_hi + off);
    uint4* dl = reinterpret_cast<uint4*>(g_WT_lo + off);
    dh[0] = make_uint4(H[0], H[1], H[2], H[3]);
    dh[1] = make_uint4(H[4], H[5], H[6], H[7]);
    dl[0] = make_uint4(L[0], L[1], L[2], L[3]);
    dl[1] = make_uint4(L[4], L[5], L[6], L[7]);
}

// ---------------- Kernel A2: bitpack adjacency -------------------------------
__global__ __launch_bounds__(256) void bitpack_k(const int* __restrict__ adj) {
    const int w = blockIdx.x * 256 + threadIdx.x;
    const int4* p = reinterpret_cast<const int4*>(adj) + (size_t)w * 8;
    unsigned bits = 0;
#pragma unroll
    for (int k = 0; k < 8; k++) {
        int4 v = p[k];
        bits |= (unsigned)(v.x != 0) << (k * 4 + 0);
        bits |= (unsigned)(v.y != 0) << (k * 4 + 1);
        bits |= (unsigned)(v.z != 0) << (k * 4 + 2);
        bits |= (unsigned)(v.w != 0) << (k * 4 + 3);
    }
    g_adjbits[w] = bits;
}

// ---------------- Kernel G: HMMA Wh GEMM + fused WhT/e1/e2/max epilogue ------
#define GB_OFF    40960
#define GB_PLANE  34816
#define GB_STRIDE 544
#define GSA_OFF   (GB_OFF + 2 * GB_PLANE)      // 110592
#define GSM_TOTAL (GSA_OFF + 512)              // 111104

__global__ __launch_bounds__(256) void gemm_mma_k(const float* __restrict__ av) {
    extern __shared__ __align__(16) char dsm[];
    float* sa = reinterpret_cast<float*>(dsm + GSA_OFF);

    const int t    = threadIdx.x;
    const int lane = t & 31;
    const int w    = t >> 5;
    const int bm   = blockIdx.x;
    const int bn   = blockIdx.y;
    const int m0   = bm * 64;
    const int wm   = w >> 1;
    const int wc   = w & 1;
    const int r0   = lane >> 2;
    const int c0   = (lane & 3) * 2;

    if (t < 32)
        reinterpret_cast<float4*>(sa)[t] =
            reinterpret_cast<const float4*>(av + bn * 128)[t];

    // one-time B staging
    {
        const int brow = t >> 2, bseg = t & 3;
        const uint32_t bdst = s2u(dsm) + GB_OFF + brow * GB_STRIDE;
        const __nv_bfloat16* bsh = g_WT_hi + (size_t)(bn * 64 + brow) * 256;
        const __nv_bfloat16* bsl = g_WT_lo + (size_t)(bn * 64 + brow) * 256;
#pragma unroll
        for (int q = 0; q < 8; q++) {
            const int seg = bseg + q * 4;
            cp16(bdst + seg * 16,            bsh + seg * 8);
            cp16(bdst + GB_PLANE + seg * 16, bsl + seg * 8);
        }
    }
    cp_commit();

    const int cprow = t >> 2, cpseg = t & 3;
    const __nv_bfloat16* xh = g_Xh + (size_t)(m0 + cprow) * 256 + cpseg * 8;
    const __nv_bfloat16* xl = g_Xl + (size_t)(m0 + cprow) * 256 + cpseg * 8;
    const uint32_t adst = s2u(dsm) + cprow * 80 + cpseg * 16;
#define CP_A(S)                                                               \
    {                                                                         \
        uint32_t sl = ((uint32_t)(S) & 3u) * 10240u;                          \
        cp16(adst + sl,        xh + (S) * 32);                                \
        cp16(adst + sl + 5120, xl + (S) * 32);                                \
    }
    CP_A(0) cp_commit();
    CP_A(1) cp_commit();
    CP_A(2) cp_commit();

    float acc[4][4];
#pragma unroll
    for (int nt = 0; nt < 4; nt++)
#pragma unroll
        for (int q = 0; q < 4; q++) acc[nt][q] = 0.f;

    const uint32_t abase = s2u(dsm) + (wm * 16 + r0) * 80 + c0 * 4;
    const uint32_t bbase = s2u(dsm) + GB_OFF + (wc * 32 + r0) * GB_STRIDE + c0 * 4;

    for (int s = 0; s < 8; s++) {
        cp_wait<2>();
        __syncthreads();
        if (s < 5) CP_A(s + 3)
        cp_commit();
        const uint32_t ab = abase + ((uint32_t)s & 3u) * 10240u;
#pragma unroll
        for (int ck = 0; ck < 2; ck++) {
            uint2 Ah0 = lds64(ab + ck * 32);
            uint2 Ah1 = lds64(ab + ck * 32 + 8 * 80);
            uint2 Al0 = lds64(ab + 5120 + ck * 32);
            uint2 Al1 = lds64(ab + 5120 + ck * 32 + 8 * 80);
            const uint32_t bk = bbase + (s * 32 + ck * 16) * 2;
#pragma unroll
            for (int nt = 0; nt < 4; nt++) {
                uint2 Bh = lds64(bk + nt * 8 * GB_STRIDE);
                uint2 Bl = lds64(bk + nt * 8 * GB_STRIDE + GB_PLANE);
                mma16816(acc[nt], Ah0.x, Ah1.x, Ah0.y, Ah1.y, Bh.x, Bh.y);
                mma16816(acc[nt], Ah0.x, Ah1.x, Ah0.y, Ah1.y, Bl.x, Bl.y);
                mma16816(acc[nt], Al0.x, Al1.x, Al0.y, Al1.y, Bh.x, Bh.y);
            }
        }
    }
#undef CP_A
    __syncthreads();

    // epilogue: stage Wh tile as sT[c][m] fp32 (aliases A ring)
    float* sT = reinterpret_cast<float*>(dsm);           // [64][68]
#pragma unroll
    for (int nt = 0; nt < 4; nt++) {
        const int c = wc * 32 + nt * 8 + c0;
        const int m = wm * 16 + r0;
        sT[(c + 0) * 68 + m]     = acc[nt][0];
        sT[(c + 1) * 68 + m]     = acc[nt][1];
        sT[(c + 0) * 68 + m + 8] = acc[nt][2];
        sT[(c + 1) * 68 + m + 8] = acc[nt][3];
    }
    __syncthreads();

    // (a) transposed fp16 hi/lo WhT write (layout gat_mma reads)
    {
        const int c   = t >> 2;
        const int seg = t & 3;
        const int b   = bm >> 4;
        const int n0  = (bm & 15) * 64 + seg * 16;
        const int h   = 2 * bn + (c >> 5);
        const int d   = c & 31;
        float v[16];
        const float4* rp = reinterpret_cast<const float4*>(&sT[c * 68 + seg * 16]);
#pragma unroll
        for (int q = 0; q < 4; q++) {
            float4 f = rp[q];
            v[q * 4 + 0] = f.x; v[q * 4 + 1] = f.y;
            v[q * 4 + 2] = f.z; v[q * 4 + 3] = f.w;
        }
        uint32_t H[8], L[8];
        split16h(v, H, L);
        const size_t off = (size_t)(b * 8 + h) * 32768 + (size_t)d * 1024 + n0;
        uint4* dh = reinterpret_cast<uint4*>(g_WhT_hi + off);
        uint4* dl = reinterpret_cast<uint4*>(g_WhT_lo + off);
        dh[0] = make_uint4(H[0], H[1], H[2], H[3]);
        dh[1] = make_uint4(H[4], H[5], H[6], H[7]);
        dl[0] = make_uint4(L[0], L[1], L[2], L[3]);
        dl[1] = make_uint4(L[4], L[5], L[6], L[7]);
    }

    // (b) e1/e2 + per-bh max atomics
    if (t < 128) {
        const int hh = t >> 6, r = t & 63;
        float e1 = 0.f, e2 = 0.f;
#pragma unroll
        for (int d = 0; d < 32; d++) {
            float v = sT[(hh * 32 + d) * 68 + r];
            e1 = fmaf(v, sa[hh * 64 + d], e1);
            e2 = fmaf(v, sa[hh * 64 + 32 + d], e2);
        }
        const int m  = m0 + r;
        const int b  = m >> 10, n = m & 1023;
        const int bh = b * 8 + bn * 2 + hh;
        g_e1[bh * 1024 + n] = e1;
        g_e2[bh * 1024 + n] = e2;

        float m1 = e1, m2 = e2;
#pragma unroll
        for (int off = 16; off; off >>= 1) {
            m1 = fmaxf(m1, __shfl_xor_sync(0xffffffffu, m1, off));
            m2 = fmaxf(m2, __shfl_xor_sync(0xffffffffu, m2, off));
        }
        if (lane == 0) {
            atomicMax(&g_M1u[bh], encf(m1));
            atomicMax(&g_M2u[bh], encf(m2));
        }
    }
}

// ---------------- Kernel E: per-j softmax factor pairs -----------------------
__global__ __launch_bounds__(256) void expj_k() {
    const int idx = blockIdx.x * 256 + threadIdx.x;     // 65536
    const int bh  = idx >> 10;
    const float M1 = decf(g_M1u[bh]);
    const float M2 = decf(g_M2u[bh]);
    const float s  = M1 + M2;
    const float C  = fmaxf(s, 0.2f * s);
    const float e2 = g_e2[idx];
    float2 r;
    r.x = __expf(e2 - C + M1);
    r.y = __expf(fmaf(0.2f, e2, fmaf(0.2f, M1, -C)));
    reinterpret_cast<float2*>(g_E2f)[idx] = r;
}

// ---------------- Kernel D: HMMA fused softmax + attn@Wh ---------------------
// Grid (4 i-tiles x 256 rows, 64 bh) = 256 blocks -> SINGLE WAVE at occ 2.
// Each warp handles two row-groups (i0+w*16.., i0+128+w*16..) against the SAME
// staged B chunk: LDS/cp.async reused, 2x MMA density per byte staged.
__global__ __launch_bounds__(256, 2) void gat_mma_k(const float* __restrict__ bias,
                                                    float* __restrict__ out) {
    __shared__ __align__(16) __half sB[4][2][32][72];   // [slot][hi/lo][d][j]

    const int t    = threadIdx.x;
    const int w    = t >> 5;
    const int lane = t & 31;
    const int bh   = blockIdx.y;
    const int b    = bh >> 3, h = bh & 7;
    const int i0   = blockIdx.x * 256;

    const int r0 = lane >> 2;
    const int c0 = (lane & 3) * 2;

    const int   row0 = w * 16 + r0;
    const float M1   = decf(g_M1u[bh]);
    const float M2   = decf(g_M2u[bh]);
    const float s    = M1 + M2;
    const float BPM  = (s >= 0.f) ? 1.f : __expf(0.8f * s);   // max_j Bp
    const float BMM  = (s >= 0.f) ? __expf(-0.8f * s) : 1.f;  // max_j Bm
    float Ap0, Am0, Ap1, Am1, Ap2, Am2, Ap3, Am3;
    {
        const float e1_0 = g_e1[bh * 1024 + i0 + row0];
        const float e1_1 = g_e1[bh * 1024 + i0 + row0 + 8];
        const float e1_2 = g_e1[bh * 1024 + i0 + row0 + 128];
        const float e1_3 = g_e1[bh * 1024 + i0 + row0 + 136];
        Ap0 = __expf(e1_0 - M1); Am0 = __expf(0.2f * (e1_0 - M1));
        Ap1 = __expf(e1_1 - M1); Am1 = __expf(0.2f * (e1_1 - M1));
        Ap2 = __expf(e1_2 - M1); Am2 = __expf(0.2f * (e1_2 - M1));
        Ap3 = __expf(e1_3 - M1); Am3 = __expf(0.2f * (e1_3 - M1));
        float rs0 = 1.f / fmaxf(Ap0 * BPM, Am0 * BMM);
        float rs1 = 1.f / fmaxf(Ap1 * BPM, Am1 * BMM);
        float rs2 = 1.f / fmaxf(Ap2 * BPM, Am2 * BMM);
        float rs3 = 1.f / fmaxf(Ap3 * BPM, Am3 * BMM);
        Ap0 *= rs0; Am0 *= rs0;  Ap1 *= rs1; Am1 *= rs1;
        Ap2 *= rs2; Am2 *= rs2;  Ap3 *= rs3; Am3 *= rs3;
    }

    const unsigned* __restrict__ mrow0 = g_adjbits + (size_t)(b * 1024 + i0 + row0) * 32;
    const unsigned* __restrict__ mrow1 = mrow0 + 8 * 32;
    const unsigned* __restrict__ mrow2 = mrow0 + 128 * 32;
    const unsigned* __restrict__ mrow3 = mrow0 + 136 * 32;
    const float* __restrict__ e2f = g_E2f + (size_t)bh * 2048;

    const int cpd = t >> 3, cpj = (t & 7) * 8;
    const __half* bsrc_hi = g_WhT_hi + (size_t)bh * 32768 + cpd * 1024 + cpj;
    const __half* bsrc_lo = g_WhT_lo + (size_t)bh * 32768 + cpd * 1024 + cpj;
#define CP_B(C_)                                                              \
    {                                                                         \
        int sl = (C_) & 3;                                                    \
        cp16(s2u(&sB[sl][0][cpd][cpj]), bsrc_hi + (C_) * 64);                 \
        cp16(s2u(&sB[sl][1][cpd][cpj]), bsrc_lo + (C_) * 64);                 \
    }
    CP_B(0) cp_commit();
    CP_B(1) cp_commit();
    CP_B(2) cp_commit();

    float accA[4][4], accB[4][4];
#pragma unroll
    for (int nt = 0; nt < 4; nt++)
#pragma unroll
        for (int q = 0; q < 4; q++) { accA[nt][q] = 0.f; accB[nt][q] = 0.f; }
    float den0 = 0.f, den1 = 0.f, den2 = 0.f, den3 = 0.f;

    for (int c = 0; c < 16; c++) {
        cp_wait<2>();
        __syncthreads();
        if (c < 13) CP_B(c + 3)
        cp_commit();
        const int sl = c & 3;

        const unsigned m0a = mrow0[2 * c], m0b = mrow0[2 * c + 1];
        const unsigned m1a = mrow1[2 * c], m1b = mrow1[2 * c + 1];
        const unsigned m2a = mrow2[2 * c], m2b = mrow2[2 * c + 1];
        const unsigned m3a = mrow3[2 * c], m3b = mrow3[2 * c + 1];

#pragma unroll
        for (int kt = 0; kt < 4; kt++) {
            const int jb = c * 64 + kt * 16;
            float4 F0 = *reinterpret_cast<const float4*>(e2f + 2 * (jb + c0));
            float4 F1 = *reinterpret_cast<const float4*>(e2f + 2 * (jb + c0 + 8));
            const int sh = ((kt & 1) * 16) + c0;
            const unsigned bits0 = ((kt >> 1) ? m0b : m0a) >> sh;
            const unsigned bits1 = ((kt >> 1) ? m1b : m1a) >> sh;
            const unsigned bits2 = ((kt >> 1) ? m2b : m2a) >> sh;
            const unsigned bits3 = ((kt >> 1) ? m3b : m3a) >> sh;

#define PP(DST, AP, AM, BP, BM, BITS, POS)                                    \
            float DST;                                                        \
            {                                                                 \
                float pe = fmaxf((AP) * (BP), (AM) * (BM));                   \
                DST = (((BITS) >> (POS)) & 1u) ? pe : 0.f;                    \
            }
            // tile A (rows row0, row0+8)
            PP(p00, Ap0, Am0, F0.x, F0.y, bits0, 0)
            PP(p01, Ap0, Am0, F0.z, F0.w, bits0, 1)
            PP(p08, Ap0, Am0, F1.x, F1.y, bits0, 8)
            PP(p09, Ap0, Am0, F1.z, F1.w, bits0, 9)
            PP(p10, Ap1, Am1, F0.x, F0.y, bits1, 0)
            PP(p11, Ap1, Am1, F0.z, F0.w, bits1, 1)
            PP(p18, Ap1, Am1, F1.x, F1.y, bits1, 8)
            PP(p19, Ap1, Am1, F1.z, F1.w, bits1, 9)
            // tile B (rows row0+128, row0+136)
            PP(q00, Ap2, Am2, F0.x, F0.y, bits2, 0)
            PP(q01, Ap2, Am2, F0.z, F0.w, bits2, 1)
            PP(q08, Ap2, Am2, F1.x, F1.y, bits2, 8)
            PP(q09, Ap2, Am2, F1.z, F1.w, bits2, 9)
            PP(q10, Ap3, Am3, F0.x, F0.y, bits3, 0)
            PP(q11, Ap3, Am3, F0.z, F0.w, bits3, 1)
            PP(q18, Ap3, Am3, F1.x, F1.y, bits3, 8)
            PP(q19, Ap3, Am3, F1.z, F1.w, bits3, 9)
#undef PP
            den0 += (p00 + p01) + (p08 + p09);
            den1 += (p10 + p11) + (p18 + p19);
            den2 += (q00 + q01) + (q08 + q09);
            den3 += (q10 + q11) + (q18 + q19);

            uint32_t a0 = cvt2h(p00, p01);
            uint32_t a1 = cvt2h(p10, p11);
            uint32_t a2 = cvt2h(p08, p09);
            uint32_t a3 = cvt2h(p18, p19);
            uint32_t b0 = cvt2h(q00, q01);
            uint32_t b1 = cvt2h(q10, q11);
            uint32_t b2 = cvt2h(q08, q09);
            uint32_t b3 = cvt2h(q18, q19);

#pragma unroll
            for (int nt = 0; nt < 4; nt++) {
                uint2 bhp = *reinterpret_cast<const uint2*>(
                    &sB[sl][0][nt * 8 + r0][kt * 16 + c0 * 2]);
                uint2 blp = *reinterpret_cast<const uint2*>(
                    &sB[sl][1][nt * 8 + r0][kt * 16 + c0 * 2]);
                mma16816h(accA[nt], a0, a1, a2, a3, bhp.x, bhp.y);
                mma16816h(accA[nt], a0, a1, a2, a3, blp.x, blp.y);
                mma16816h(accB[nt], b0, b1, b2, b3, bhp.x, bhp.y);
                mma16816h(accB[nt], b0, b1, b2, b3, blp.x, blp.y);
            }
        }
    }
#undef CP_B

    den0 += __shfl_xor_sync(0xffffffffu, den0, 1);
    den0 += __shfl_xor_sync(0xffffffffu, den0, 2);
    den1 += __shfl_xor_sync(0xffffffffu, den1, 1);
    den1 += __shfl_xor_sync(0xffffffffu, den1, 2);
    den2 += __shfl_xor_sync(0xffffffffu, den2, 1);
    den2 += __shfl_xor_sync(0xffffffffu, den2, 2);
    den3 += __shfl_xor_sync(0xffffffffu, den3, 1);
    den3 += __shfl_xor_sync(0xffffffffu, den3, 2);
    const float rd0 = 1.0f / den0;
    const float rd1 = 1.0f / den1;
    const float rd2 = 1.0f / den2;
    const float rd3 = 1.0f / den3;

    float* o0 = out + ((size_t)(b * 1024 + i0 + row0)) * 256 + h * 32;
    float* o1 = o0 + 8 * 256;
    float* o2 = o0 + 128 * 256;
    float* o3 = o0 + 136 * 256;
#pragma unroll
    for (int nt = 0; nt < 4; nt++) {
        const int dcol = nt * 8 + c0;
        float2 bi = *reinterpret_cast<const float2*>(bias + h * 32 + dcol);
        float2 v0, v1, v2, v3;
        v0.x = fmaxf(accA[nt][0] * rd0 + bi.x, 0.f);
        v0.y = fmaxf(accA[nt][1] * rd0 + bi.y, 0.f);
        v1.x = fmaxf(accA[nt][2] * rd1 + bi.x, 0.f);
        v1.y = fmaxf(accA[nt][3] * rd1 + bi.y, 0.f);
        v2.x = fmaxf(accB[nt][0] * rd2 + bi.x, 0.f);
        v2.y = fmaxf(accB[nt][1] * rd2 + bi.y, 0.f);
        v3.x = fmaxf(accB[nt][2] * rd3 + bi.x, 0.f);
        v3.y = fmaxf(accB[nt][3] * rd3 + bi.y, 0.f);
        *reinterpret_cast<float2*>(o0 + dcol) = v0;
        *reinterpret_cast<float2*>(o1 + dcol) = v1;
        *reinterpret_cast<float2*>(o2 + dcol) = v2;
        *reinterpret_cast<float2*>(o3 + dcol) = v3;
    }
}

// ---------------- launcher ---------------------------------------------------
extern "C" void kernel_launch(void* const* d_in, const int* in_sizes, int n_in,
                              void* d_out, int out_size) {
    const float* nf   = (const float*)d_in[0];   // (8,1024,256)
    const int*   adj  = (const int*)d_in[1];     // (8,1024,1024)
    const float* W    = (const float*)d_in[2];   // (8,256,32)
    const float* a    = (const float*)d_in[3];   // (8,64)
    const float* bias = (const float*)d_in[4];   // (256,)
    float*       out  = (float*)d_out;           // (8,1024,256)

    cudaFuncSetAttribute(gemm_mma_k, cudaFuncAttributeMaxDynamicSharedMemorySize,
                         GSM_TOTAL);

    split_x_k<<<512, 256>>>(nf);
    split_w_k<<<16, 256>>>(W);
    bitpack_k<<<1024, 256>>>(adj);
    gemm_mma_k<<<dim3(128, 4), 256, GSM_TOTAL>>>(a);
    expj_k<<<256, 256>>>();
    gat_mma_k<<<dim3(4, 64), 256>>>(bias, out);
}

// round 15
// speedup vs baseline: 3.2416x; 1.1037x over previous
#include <cuda_runtime.h>
#include <cuda_bf16.h>
#include <cuda_fp16.h>
#include <cstdint>
#include <cstddef>

typedef unsigned long long ull;

// ---------------- scratch (static device globals; no runtime alloc) ----------
__device__ __align__(16) float g_e1[65536];            // [(b*8+h)*1024 + n]
__device__ __align__(16) float g_e2[65536];
__device__ __align__(16) float g_E2f[65536 * 2];       // per-j factor pair (Bp,Bm)
__device__ __align__(16) unsigned g_M1u[64];           // per-bh max e1 (encoded)
__device__ __align__(16) unsigned g_M2u[64];           // per-bh max e2 (encoded)
__device__ __align__(16) unsigned g_adjbits[8 * 1024 * 32];          // 1 MB
// k-pair-interleaved bf16 splits for the Wh GEMM inputs
__device__ __align__(16) __nv_bfloat16 g_Xh[8192 * 256];             // [m][k]
__device__ __align__(16) __nv_bfloat16 g_Xl[8192 * 256];
__device__ __align__(16) __nv_bfloat16 g_WT_hi[256 * 256];           // [h*32+d][k]
__device__ __align__(16) __nv_bfloat16 g_WT_lo[256 * 256];
// WhT for attention GEMM: single fp16, [bh][d][n], j-pair interleaved
__device__ __align__(16) __half g_WhT_hi[64 * 32 * 1024];

// ---------------- small PTX helpers ------------------------------------------
__device__ __forceinline__ uint32_t s2u(const void* p) {
    return (uint32_t)__cvta_generic_to_shared(p);
}
__device__ __forceinline__ void cp16(uint32_t dst, const void* src) {
    asm volatile("cp.async.cg.shared.global [%0], [%1], 16;" :: "r"(dst), "l"(src));
}
__device__ __forceinline__ void cp_commit() { asm volatile("cp.async.commit_group;"); }
template <int N> __device__ __forceinline__ void cp_wait() {
    asm volatile("cp.async.wait_group %0;" :: "n"(N));
}
// pack: low half = bf16(l), high half = bf16(h)
__device__ __forceinline__ uint32_t cvt2bf(float h, float l) {
    uint32_t r; asm("cvt.rn.bf16x2.f32 %0, %1, %2;" : "=r"(r) : "f"(h), "f"(l)); return r;
}
// pack two fp32 -> f16x2, low half = a
__device__ __forceinline__ uint32_t cvt2h(float a, float b) {
    uint32_t r; asm("cvt.rn.f16x2.f32 %0, %1, %2;" : "=r"(r) : "f"(b), "f"(a)); return r;
}
__device__ __forceinline__ uint2 lds64(uint32_t a) {
    uint2 v;
    asm volatile("ld.shared.v2.b32 {%0,%1}, [%2];" : "=r"(v.x), "=r"(v.y) : "r"(a));
    return v;
}
// D(16x8,f32) += A(16x16,bf16,row) * B(16x8,bf16,col)
__device__ __forceinline__ void mma16816(float* d,
                                         uint32_t a0, uint32_t a1, uint32_t a2, uint32_t a3,
                                         uint32_t b0, uint32_t b1) {
    asm volatile(
        "mma.sync.aligned.m16n8k16.row.col.f32.bf16.bf16.f32 "
        "{%0,%1,%2,%3}, {%4,%5,%6,%7}, {%8,%9}, {%0,%1,%2,%3};"
        : "+f"(d[0]), "+f"(d[1]), "+f"(d[2]), "+f"(d[3])
        : "r"(a0), "r"(a1), "r"(a2), "r"(a3), "r"(b0), "r"(b1));
}
// fp16 variant
__device__ __forceinline__ void mma16816h(float* d,
                                          uint32_t a0, uint32_t a1, uint32_t a2, uint32_t a3,
                                          uint32_t b0, uint32_t b1) {
    asm volatile(
        "mma.sync.aligned.m16n8k16.row.col.f32.f16.f16.f32 "
        "{%0,%1,%2,%3}, {%4,%5,%6,%7}, {%8,%9}, {%0,%1,%2,%3};"
        : "+f"(d[0]), "+f"(d[1]), "+f"(d[2]), "+f"(d[3])
        : "r"(a0), "r"(a1), "r"(a2), "r"(a3), "r"(b0), "r"(b1));
}
// monotone float<->uint encoding for atomicMax over signed floats
__device__ __forceinline__ unsigned encf(float f) {
    unsigned u = __float_as_uint(f);
    return (u & 0x80000000u) ? ~u : (u | 0x80000000u);
}
__device__ __forceinline__ float decf(unsigned k) {
    unsigned u = (k & 0x80000000u) ? (k ^ 0x80000000u) : ~k;
    return __uint_as_float(u);
}
// split 16 fp32 -> 8 hi + 8 lo bf16x2 words, k-pair interleaved
__device__ __forceinline__ void split16(const float* v, uint32_t* H, uint32_t* L) {
    const int perm[8] = {0, 8, 2, 10, 4, 12, 6, 14};
#pragma unroll
    for (int m = 0; m < 8; m++) {
        float f0 = v[perm[m]], f1 = v[perm[m] + 1];
        uint32_t hw = cvt2bf(f1, f0);
        float r0 = f0 - __uint_as_float(hw << 16);
        float r1 = f1 - __uint_as_float(hw & 0xffff0000u);
        H[m] = hw;
        L[m] = cvt2bf(r1, r0);
    }
}

// ---------------- Kernel P1: split X fp32 -> bf16 hi/lo (interleaved) --------
__global__ __launch_bounds__(256) void split_x_k(const float* __restrict__ X) {
    const int g = blockIdx.x * 256 + threadIdx.x;
    float v[16];
    const float4* s4 = reinterpret_cast<const float4*>(X + (size_t)g * 16);
#pragma unroll
    for (int q = 0; q < 4; q++) {
        float4 f = s4[q];
        v[q * 4 + 0] = f.x; v[q * 4 + 1] = f.y;
        v[q * 4 + 2] = f.z; v[q * 4 + 3] = f.w;
    }
    uint32_t H[8], L[8];
    split16(v, H, L);
    uint4* dh = reinterpret_cast<uint4*>(g_Xh + (size_t)g * 16);
    uint4* dl = reinterpret_cast<uint4*>(g_Xl + (size_t)g * 16);
    dh[0] = make_uint4(H[0], H[1], H[2], H[3]);
    dh[1] = make_uint4(H[4], H[5], H[6], H[7]);
    dl[0] = make_uint4(L[0], L[1], L[2], L[3]);
    dl[1] = make_uint4(L[4], L[5], L[6], L[7]);
}

// ---------------- Kernel P2: split/transpose W + init max keys ---------------
__global__ __launch_bounds__(256) void split_w_k(const float* __restrict__ W) {
    const int t = threadIdx.x;
    if (blockIdx.x == 0 && t < 64) { g_M1u[t] = 0u; g_M2u[t] = 0u; }
    const int task = blockIdx.x * 256 + t;
    const int h   = task >> 9;
    const int d   = (task >> 4) & 31;
    const int grp = task & 15;
    const float* wp = W + (size_t)h * 8192 + (size_t)grp * 16 * 32 + d;
    float v[16];
#pragma unroll
    for (int k = 0; k < 16; k++) v[k] = wp[k * 32];
    uint32_t H[8], L[8];
    split16(v, H, L);
    const size_t off = (size_t)(h * 32 + d) * 256 + grp * 16;
    uint4* dh = reinterpret_cast<uint4*>(g_WT_hi + off);
    uint4* dl = reinterpret_cast<uint4*>(g_WT_lo + off);
    dh[0] = make_uint4(H[0], H[1], H[2], H[3]);
    dh[1] = make_uint4(H[4], H[5], H[6], H[7]);
    dl[0] = make_uint4(L[0], L[1], L[2], L[3]);
    dl[1] = make_uint4(L[4], L[5], L[6], L[7]);
}

// ---------------- Kernel A2: bitpack adjacency -------------------------------
__global__ __launch_bounds__(256) void bitpack_k(const int* __restrict__ adj) {
    const int w = blockIdx.x * 256 + threadIdx.x;
    const int4* p = reinterpret_cast<const int4*>(adj) + (size_t)w * 8;
    unsigned bits = 0;
#pragma unroll
    for (int k = 0; k < 8; k++) {
        int4 v = p[k];
        bits |= (unsigned)(v.x != 0) << (k * 4 + 0);
        bits |= (unsigned)(v.y != 0) << (k * 4 + 1);
        bits |= (unsigned)(v.z != 0) << (k * 4 + 2);
        bits |= (unsigned)(v.w != 0) << (k * 4 + 3);
    }
    g_adjbits[w] = bits;
}

// ---------------- Kernel G: HMMA Wh GEMM + fused WhT/e1/e2/max epilogue ------
#define GB_OFF    40960
#define GB_PLANE  34816
#define GB_STRIDE 544
#define GSA_OFF   (GB_OFF + 2 * GB_PLANE)      // 110592
#define GSM_TOTAL (GSA_OFF + 512)              // 111104

__global__ __launch_bounds__(256) void gemm_mma_k(const float* __restrict__ av) {
    extern __shared__ __align__(16) char dsm[];
    float* sa = reinterpret_cast<float*>(dsm + GSA_OFF);

    const int t    = threadIdx.x;
    const int lane = t & 31;
    const int w    = t >> 5;
    const int bm   = blockIdx.x;
    const int bn   = blockIdx.y;
    const int m0   = bm * 64;
    const int wm   = w >> 1;
    const int wc   = w & 1;
    const int r0   = lane >> 2;
    const int c0   = (lane & 3) * 2;

    if (t < 32)
        reinterpret_cast<float4*>(sa)[t] =
            reinterpret_cast<const float4*>(av + bn * 128)[t];

    // one-time B staging
    {
        const int brow = t >> 2, bseg = t & 3;
        const uint32_t bdst = s2u(dsm) + GB_OFF + brow * GB_STRIDE;
        const __nv_bfloat16* bsh = g_WT_hi + (size_t)(bn * 64 + brow) * 256;
        const __nv_bfloat16* bsl = g_WT_lo + (size_t)(bn * 64 + brow) * 256;
#pragma unroll
        for (int q = 0; q < 8; q++) {
            const int seg = bseg + q * 4;
            cp16(bdst + seg * 16,            bsh + seg * 8);
            cp16(bdst + GB_PLANE + seg * 16, bsl + seg * 8);
        }
    }
    cp_commit();

    const int cprow = t >> 2, cpseg = t & 3;
    const __nv_bfloat16* xh = g_Xh + (size_t)(m0 + cprow) * 256 + cpseg * 8;
    const __nv_bfloat16* xl = g_Xl + (size_t)(m0 + cprow) * 256 + cpseg * 8;
    const uint32_t adst = s2u(dsm) + cprow * 80 + cpseg * 16;
#define CP_A(S)                                                               \
    {                                                                         \
        uint32_t sl = ((uint32_t)(S) & 3u) * 10240u;                          \
        cp16(adst + sl,        xh + (S) * 32);                                \
        cp16(adst + sl + 5120, xl + (S) * 32);                                \
    }
    CP_A(0) cp_commit();
    CP_A(1) cp_commit();
    CP_A(2) cp_commit();

    float acc[4][4];
#pragma unroll
    for (int nt = 0; nt < 4; nt++)
#pragma unroll
        for (int q = 0; q < 4; q++) acc[nt][q] = 0.f;

    const uint32_t abase = s2u(dsm) + (wm * 16 + r0) * 80 + c0 * 4;
    const uint32_t bbase = s2u(dsm) + GB_OFF + (wc * 32 + r0) * GB_STRIDE + c0 * 4;

    for (int s = 0; s < 8; s++) {
        cp_wait<2>();
        __syncthreads();
        if (s < 5) CP_A(s + 3)
        cp_commit();
        const uint32_t ab = abase + ((uint32_t)s & 3u) * 10240u;
#pragma unroll
        for (int ck = 0; ck < 2; ck++) {
            uint2 Ah0 = lds64(ab + ck * 32);
            uint2 Ah1 = lds64(ab + ck * 32 + 8 * 80);
            uint2 Al0 = lds64(ab + 5120 + ck * 32);
            uint2 Al1 = lds64(ab + 5120 + ck * 32 + 8 * 80);
            const uint32_t bk = bbase + (s * 32 + ck * 16) * 2;
#pragma unroll
            for (int nt = 0; nt < 4; nt++) {
                uint2 Bh = lds64(bk + nt * 8 * GB_STRIDE);
                uint2 Bl = lds64(bk + nt * 8 * GB_STRIDE + GB_PLANE);
                mma16816(acc[nt], Ah0.x, Ah1.x, Ah0.y, Ah1.y, Bh.x, Bh.y);
                mma16816(acc[nt], Ah0.x, Ah1.x, Ah0.y, Ah1.y, Bl.x, Bl.y);
                mma16816(acc[nt], Al0.x, Al1.x, Al0.y, Al1.y, Bh.x, Bh.y);
            }
        }
    }
#undef CP_A
    __syncthreads();

    // epilogue: stage Wh tile as sT[c][m] fp32 (aliases A ring)
    float* sT = reinterpret_cast<float*>(dsm);           // [64][68]
#pragma unroll
    for (int nt = 0; nt < 4; nt++) {
        const int c = wc * 32 + nt * 8 + c0;
        const int m = wm * 16 + r0;
        sT[(c + 0) * 68 + m]     = acc[nt][0];
        sT[(c + 1) * 68 + m]     = acc[nt][1];
        sT[(c + 0) * 68 + m + 8] = acc[nt][2];
        sT[(c + 1) * 68 + m + 8] = acc[nt][3];
    }
    __syncthreads();

    // (a) transposed single-fp16 WhT write (layout gat_mma reads)
    {
        const int c   = t >> 2;
        const int seg = t & 3;
        const int b   = bm >> 4;
        const int n0  = (bm & 15) * 64 + seg * 16;
        const int h   = 2 * bn + (c >> 5);
        const int d   = c & 31;
        float v[16];
        const float4* rp = reinterpret_cast<const float4*>(&sT[c * 68 + seg * 16]);
#pragma unroll
        for (int q = 0; q < 4; q++) {
            float4 f = rp[q];
            v[q * 4 + 0] = f.x; v[q * 4 + 1] = f.y;
            v[q * 4 + 2] = f.z; v[q * 4 + 3] = f.w;
        }
        const int perm[8] = {0, 8, 2, 10, 4, 12, 6, 14};
        uint32_t H[8];
#pragma unroll
        for (int m = 0; m < 8; m++)
            H[m] = cvt2h(v[perm[m]], v[perm[m] + 1]);   // low half = first elem
        const size_t off = (size_t)(b * 8 + h) * 32768 + (size_t)d * 1024 + n0;
        uint4* dh = reinterpret_cast<uint4*>(g_WhT_hi + off);
        dh[0] = make_uint4(H[0], H[1], H[2], H[3]);
        dh[1] = make_uint4(H[4], H[5], H[6], H[7]);
    }

    // (b) e1/e2 + per-bh max atomics
    if (t < 128) {
        const int hh = t >> 6, r = t & 63;
        float e1 = 0.f, e2 = 0.f;
#pragma unroll
        for (int d = 0; d < 32; d++) {
            float v = sT[(hh * 32 + d) * 68 + r];
            e1 = fmaf(v, sa[hh * 64 + d], e1);
            e2 = fmaf(v, sa[hh * 64 + 32 + d], e2);
        }
        const int m  = m0 + r;
        const int b  = m >> 10, n = m & 1023;
        const int bh = b * 8 + bn * 2 + hh;
        g_e1[bh * 1024 + n] = e1;
        g_e2[bh * 1024 + n] = e2;

        float m1 = e1, m2 = e2;
#pragma unroll
        for (int off = 16; off; off >>= 1) {
            m1 = fmaxf(m1, __shfl_xor_sync(0xffffffffu, m1, off));
            m2 = fmaxf(m2, __shfl_xor_sync(0xffffffffu, m2, off));
        }
        if (lane == 0) {
            atomicMax(&g_M1u[bh], encf(m1));
            atomicMax(&g_M2u[bh], encf(m2));
        }
    }
}

// ---------------- Kernel E: per-j softmax factor pairs -----------------------
__global__ __launch_bounds__(256) void expj_k() {
    const int idx = blockIdx.x * 256 + threadIdx.x;     // 65536
    const int bh  = idx >> 10;
    const float M1 = decf(g_M1u[bh]);
    const float M2 = decf(g_M2u[bh]);
    const float s  = M1 + M2;
    const float C  = fmaxf(s, 0.2f * s);
    const float e2 = g_e2[idx];
    float2 r;
    r.x = __expf(e2 - C + M1);
    r.y = __expf(fmaf(0.2f, e2, fmaf(0.2f, M1, -C)));
    reinterpret_cast<float2*>(g_E2f)[idx] = r;
}

// ---------------- Kernel D: HMMA fused softmax + attn@Wh ---------------------
// Grid (4 i-tiles x 256 rows, 64 bh) = 256 blocks, single wave at occ 2.
// Single fp16 product (P fp16 x Wh fp16): half the MMAs of R14; sB single plane.
__global__ __launch_bounds__(256, 2) void gat_mma_k(const float* __restrict__ bias,
                                                    float* __restrict__ out) {
    __shared__ __align__(16) __half sB[4][32][72];      // [slot][d][j] fp16 hi

    const int t    = threadIdx.x;
    const int w    = t >> 5;
    const int lane = t & 31;
    const int bh   = blockIdx.y;
    const int b    = bh >> 3, h = bh & 7;
    const int i0   = blockIdx.x * 256;

    const int r0 = lane >> 2;
    const int c0 = (lane & 3) * 2;

    const int   row0 = w * 16 + r0;
    const float M1   = decf(g_M1u[bh]);
    const float M2   = decf(g_M2u[bh]);
    const float s    = M1 + M2;
    const float BPM  = (s >= 0.f) ? 1.f : __expf(0.8f * s);   // max_j Bp
    const float BMM  = (s >= 0.f) ? __expf(-0.8f * s) : 1.f;  // max_j Bm
    float Ap0, Am0, Ap1, Am1, Ap2, Am2, Ap3, Am3;
    {
        const float e1_0 = g_e1[bh * 1024 + i0 + row0];
        const float e1_1 = g_e1[bh * 1024 + i0 + row0 + 8];
        const float e1_2 = g_e1[bh * 1024 + i0 + row0 + 128];
        const float e1_3 = g_e1[bh * 1024 + i0 + row0 + 136];
        Ap0 = __expf(e1_0 - M1); Am0 = __expf(0.2f * (e1_0 - M1));
        Ap1 = __expf(e1_1 - M1); Am1 = __expf(0.2f * (e1_1 - M1));
        Ap2 = __expf(e1_2 - M1); Am2 = __expf(0.2f * (e1_2 - M1));
        Ap3 = __expf(e1_3 - M1); Am3 = __expf(0.2f * (e1_3 - M1));
        float rs0 = 1.f / fmaxf(Ap0 * BPM, Am0 * BMM);
        float rs1 = 1.f / fmaxf(Ap1 * BPM, Am1 * BMM);
        float rs2 = 1.f / fmaxf(Ap2 * BPM, Am2 * BMM);
        float rs3 = 1.f / fmaxf(Ap3 * BPM, Am3 * BMM);
        Ap0 *= rs0; Am0 *= rs0;  Ap1 *= rs1; Am1 *= rs1;
        Ap2 *= rs2; Am2 *= rs2;  Ap3 *= rs3; Am3 *= rs3;
    }

    const unsigned* __restrict__ mrow0 = g_adjbits + (size_t)(b * 1024 + i0 + row0) * 32;
    const unsigned* __restrict__ mrow1 = mrow0 + 8 * 32;
    const unsigned* __restrict__ mrow2 = mrow0 + 128 * 32;
    const unsigned* __restrict__ mrow3 = mrow0 + 136 * 32;
    const float* __restrict__ e2f = g_E2f + (size_t)bh * 2048;

    const int cpd = t >> 3, cpj = (t & 7) * 8;
    const __half* bsrc_hi = g_WhT_hi + (size_t)bh * 32768 + cpd * 1024 + cpj;
#define CP_B(C_)                                                              \
    {                                                                         \
        int sl = (C_) & 3;                                                    \
        cp16(s2u(&sB[sl][cpd][cpj]), bsrc_hi + (C_) * 64);                    \
    }
    CP_B(0) cp_commit();
    CP_B(1) cp_commit();
    CP_B(2) cp_commit();

    float accA[4][4], accB[4][4];
#pragma unroll
    for (int nt = 0; nt < 4; nt++)
#pragma unroll
        for (int q = 0; q < 4; q++) { accA[nt][q] = 0.f; accB[nt][q] = 0.f; }
    float den0 = 0.f, den1 = 0.f, den2 = 0.f, den3 = 0.f;

    for (int c = 0; c < 16; c++) {
        cp_wait<2>();
        __syncthreads();
        if (c < 13) CP_B(c + 3)
        cp_commit();
        const int sl = c & 3;

        const unsigned m0a = mrow0[2 * c], m0b = mrow0[2 * c + 1];
        const unsigned m1a = mrow1[2 * c], m1b = mrow1[2 * c + 1];
        const unsigned m2a = mrow2[2 * c], m2b = mrow2[2 * c + 1];
        const unsigned m3a = mrow3[2 * c], m3b = mrow3[2 * c + 1];

#pragma unroll
        for (int kt = 0; kt < 4; kt++) {
            const int jb = c * 64 + kt * 16;
            float4 F0 = *reinterpret_cast<const float4*>(e2f + 2 * (jb + c0));
            float4 F1 = *reinterpret_cast<const float4*>(e2f + 2 * (jb + c0 + 8));
            const int sh = ((kt & 1) * 16) + c0;
            const unsigned bits0 = ((kt >> 1) ? m0b : m0a) >> sh;
            const unsigned bits1 = ((kt >> 1) ? m1b : m1a) >> sh;
            const unsigned bits2 = ((kt >> 1) ? m2b : m2a) >> sh;
            const unsigned bits3 = ((kt >> 1) ? m3b : m3a) >> sh;

#define PP(DST, AP, AM, BP, BM, BITS, POS)                                    \
            float DST;                                                        \
            {                                                                 \
                float pe = fmaxf((AP) * (BP), (AM) * (BM));                   \
                DST = (((BITS) >> (POS)) & 1u) ? pe : 0.f;                    \
            }
            PP(p00, Ap0, Am0, F0.x, F0.y, bits0, 0)
            PP(p01, Ap0, Am0, F0.z, F0.w, bits0, 1)
            PP(p08, Ap0, Am0, F1.x, F1.y, bits0, 8)
            PP(p09, Ap0, Am0, F1.z, F1.w, bits0, 9)
            PP(p10, Ap1, Am1, F0.x, F0.y, bits1, 0)
            PP(p11, Ap1, Am1, F0.z, F0.w, bits1, 1)
            PP(p18, Ap1, Am1, F1.x, F1.y, bits1, 8)
            PP(p19, Ap1, Am1, F1.z, F1.w, bits1, 9)
            PP(q00, Ap2, Am2, F0.x, F0.y, bits2, 0)
            PP(q01, Ap2, Am2, F0.z, F0.w, bits2, 1)
            PP(q08, Ap2, Am2, F1.x, F1.y, bits2, 8)
            PP(q09, Ap2, Am2, F1.z, F1.w, bits2, 9)
            PP(q10, Ap3, Am3, F0.x, F0.y, bits3, 0)
            PP(q11, Ap3, Am3, F0.z, F0.w, bits3, 1)
            PP(q18, Ap3, Am3, F1.x, F1.y, bits3, 8)
            PP(q19, Ap3, Am3, F1.z, F1.w, bits3, 9)
#undef PP
            den0 += (p00 + p01) + (p08 + p09);
            den1 += (p10 + p11) + (p18 + p19);
            den2 += (q00 + q01) + (q08 + q09);
            den3 += (q10 + q11) + (q18 + q19);

            uint32_t a0 = cvt2h(p00, p01);
            uint32_t a1 = cvt2h(p10, p11);
            uint32_t a2 = cvt2h(p08, p09);
            uint32_t a3 = cvt2h(p18, p19);
            uint32_t b0 = cvt2h(q00, q01);
            uint32_t b1 = cvt2h(q10, q11);
            uint32_t b2 = cvt2h(q08, q09);
            uint32_t b3 = cvt2h(q18, q19);

#pragma unroll
            for (int nt = 0; nt < 4; nt++) {
                uint2 bhp = *reinterpret_cast<const uint2*>(
                    &sB[sl][nt * 8 + r0][kt * 16 + c0 * 2]);
                mma16816h(accA[nt], a0, a1, a2, a3, bhp.x, bhp.y);
                mma16816h(accB[nt], b0, b1, b2, b3, bhp.x, bhp.y);
            }
        }
    }
#undef CP_B

    den0 += __shfl_xor_sync(0xffffffffu, den0, 1);
    den0 += __shfl_xor_sync(0xffffffffu, den0, 2);
    den1 += __shfl_xor_sync(0xffffffffu, den1, 1);
    den1 += __shfl_xor_sync(0xffffffffu, den1, 2);
    den2 += __shfl_xor_sync(0xffffffffu, den2, 1);
    den2 += __shfl_xor_sync(0xffffffffu, den2, 2);
    den3 += __shfl_xor_sync(0xffffffffu, den3, 1);
    den3 += __shfl_xor_sync(0xffffffffu, den3, 2);
    const float rd0 = 1.0f / den0;
    const float rd1 = 1.0f / den1;
    const float rd2 = 1.0f / den2;
    const float rd3 = 1.0f / den3;

    float* o0 = out + ((size_t)(b * 1024 + i0 + row0)) * 256 + h * 32;
    float* o1 = o0 + 8 * 256;
    float* o2 = o0 + 128 * 256;
    float* o3 = o0 + 136 * 256;
#pragma unroll
    for (int nt = 0; nt < 4; nt++) {
        const int dcol = nt * 8 + c0;
        float2 bi = *reinterpret_cast<const float2*>(bias + h * 32 + dcol);
        float2 v0, v1, v2, v3;
        v0.x = fmaxf(accA[nt][0] * rd0 + bi.x, 0.f);
        v0.y = fmaxf(accA[nt][1] * rd0 + bi.y, 0.f);
        v1.x = fmaxf(accA[nt][2] * rd1 + bi.x, 0.f);
        v1.y = fmaxf(accA[nt][3] * rd1 + bi.y, 0.f);
        v2.x = fmaxf(accB[nt][0] * rd2 + bi.x, 0.f);
        v2.y = fmaxf(accB[nt][1] * rd2 + bi.y, 0.f);
        v3.x = fmaxf(accB[nt][2] * rd3 + bi.x, 0.f);
        v3.y = fmaxf(accB[nt][3] * rd3 + bi.y, 0.f);
        *reinterpret_cast<float2*>(o0 + dcol) = v0;
        *reinterpret_cast<float2*>(o1 + dcol) = v1;
        *reinterpret_cast<float2*>(o2 + dcol) = v2;
        *reinterpret_cast<float2*>(o3 + dcol) = v3;
    }
}

// ---------------- launcher ---------------------------------------------------
extern "C" void kernel_launch(void* const* d_in, const int* in_sizes, int n_in,
                              void* d_out, int out_size) {
    const float* nf   = (const float*)d_in[0];   // (8,1024,256)
    const int*   adj  = (const int*)d_in[1];     // (8,1024,1024)
    const float* W    = (const float*)d_in[2];   // (8,256,32)
    const float* a    = (const float*)d_in[3];   // (8,64)
    const float* bias = (const float*)d_in[4];   // (256,)
    float*       out  = (float*)d_out;           // (8,1024,256)

    cudaFuncSetAttribute(gemm_mma_k, cudaFuncAttributeMaxDynamicSharedMemorySize,
                         GSM_TOTAL);

    split_x_k<<<512, 256>>>(nf);
    split_w_k<<<16, 256>>>(W);
    bitpack_k<<<1024, 256>>>(adj);
    gemm_mma_k<<<dim3(128, 4), 256, GSM_TOTAL>>>(a);
    expj_k<<<256, 256>>>();
    gat_mma_k<<<dim3(4, 64), 256>>>(bias, out);
}